// round 4
// baseline (speedup 1.0000x reference)
#include <cuda_runtime.h>
#include <cstdint>
#include <math.h>

// Problem constants
#define Nn   16384
#define Ee   65536
#define Gg   64
#define INF  63
#define HID  2048
#define MIDD 1024
#define NCLS 18
#define SLOPE 0.01f
#define EPS   1e-5f

// ---------------- scratch (device globals; no allocation allowed) ----------------
__device__ float g_nm[(size_t)Nn * HID];   // neighbor mean buffer
__device__ float g_x [(size_t)Nn * HID];   // current activations
__device__ float g_y [(size_t)Nn * HID];   // GEMM output
__device__ float g_scale[HID];
__device__ float g_shift[HID];
__device__ float g_hg[Gg * HID];
__device__ float g_t1[Gg * HID];
__device__ float g_t2[Gg * MIDD];
// CSR of incoming edges
__device__ int g_degi[Nn];
__device__ int g_cur[Nn];
__device__ int g_rowptr[Nn + 1];
__device__ int g_col[Ee];
__device__ int g_gstart[Gg + 1];
// transposed + tf32-rounded weights [N rows, K cols] (K-major)
__device__ float g_wt2s[(size_t)HID * HID];
__device__ float g_wt2n[(size_t)HID * HID];
__device__ float g_wt3s[(size_t)HID * HID];
__device__ float g_wt3n[(size_t)HID * HID];

// ==================== helpers ====================
__device__ __forceinline__ uint32_t smem_u32(const void* p) {
    uint32_t a;
    asm("{ .reg .u64 t; cvta.to.shared.u64 t, %1; cvt.u32.u64 %0, t; }" : "=r"(a) : "l"(p));
    return a;
}
__device__ __forceinline__ uint32_t f2tf32(float v) {
    uint32_t r; asm("cvt.rna.tf32.f32 %0, %1;" : "=r"(r) : "f"(v)); return r;
}
__device__ __forceinline__ void cp_async16(uint32_t dst, const void* src) {
    asm volatile("cp.async.cg.shared.global [%0], [%1], 16;" :: "r"(dst), "l"(src) : "memory");
}
__device__ __forceinline__ void cp_commit() {
    asm volatile("cp.async.commit_group;" ::: "memory");
}
__device__ __forceinline__ void mma_tf32(float* d, const uint32_t* a, const uint32_t* b) {
    asm volatile(
        "mma.sync.aligned.m16n8k8.row.col.f32.tf32.tf32.f32 "
        "{%0,%1,%2,%3}, {%4,%5,%6,%7}, {%8,%9}, {%0,%1,%2,%3};"
        : "+f"(d[0]), "+f"(d[1]), "+f"(d[2]), "+f"(d[3])
        : "r"(a[0]), "r"(a[1]), "r"(a[2]), "r"(a[3]), "r"(b[0]), "r"(b[1]));
}

// ==================== tf32 mma.sync dual-source GEMM ====================
// C[M=16384, N=2048] = A1@B1^T + A2@B2^T + bias.  K = 2048 per source.
#define PADF 36
#define OP_FLOATS (128 * PADF)
#define STAGE_FLOATS (2 * OP_FLOATS)
#define TCG_SMEM_BYTES (2 * STAGE_FLOATS * 4)     // 73728 B

__global__ void __launch_bounds__(256, 2)
tc_gemm_dual(const float* __restrict__ A1, const float* __restrict__ B1,
             const float* __restrict__ A2, const float* __restrict__ B2,
             const float* __restrict__ bias, float* __restrict__ C) {
    extern __shared__ __align__(16) float smem[];
    uint32_t sb = smem_u32(smem);
    const int tid  = threadIdx.x;
    const int wid  = tid >> 5;
    const int lane = tid & 31;
    const int rowBlk = blockIdx.y * 128;
    const int colBlk = blockIdx.x * 128;
    const int wm = (wid & 1) * 64;
    const int wn = (wid >> 1) * 32;
    const int lr = lane >> 2;
    const int lc = lane & 3;

    float acc[4][4][4];
    #pragma unroll
    for (int i = 0; i < 4; i++)
        #pragma unroll
        for (int j = 0; j < 4; j++)
            #pragma unroll
            for (int k = 0; k < 4; k++) acc[i][j][k] = 0.0f;

    const int NC  = HID / 32;
    const int TOT = 2 * NC;

    {
        #pragma unroll
        for (int i = 0; i < 4; i++) {
            int t = tid + i * 256;
            int r = t >> 3, sg = t & 7;
            uint32_t off = (uint32_t)r * (PADF * 4) + (uint32_t)sg * 16;
            cp_async16(sb + off, A1 + (size_t)(rowBlk + r) * HID + sg * 4);
            cp_async16(sb + OP_FLOATS * 4 + off, B1 + (size_t)(colBlk + r) * HID + sg * 4);
        }
        cp_commit();
    }

    for (int c = 0; c < TOT; c++) {
        int s = c & 1;
        if (c + 1 < TOT) {
            int n2 = c + 1;
            const float* A = (n2 < NC) ? A1 : A2;
            const float* B = (n2 < NC) ? B1 : B2;
            int k0 = (n2 & (NC - 1)) * 32;
            uint32_t base = sb + (uint32_t)(s ^ 1) * (STAGE_FLOATS * 4);
            #pragma unroll
            for (int i = 0; i < 4; i++) {
                int t = tid + i * 256;
                int r = t >> 3, sg = t & 7;
                uint32_t off = (uint32_t)r * (PADF * 4) + (uint32_t)sg * 16;
                cp_async16(base + off, A + (size_t)(rowBlk + r) * HID + k0 + sg * 4);
                cp_async16(base + OP_FLOATS * 4 + off, B + (size_t)(colBlk + r) * HID + k0 + sg * 4);
            }
            cp_commit();
            asm volatile("cp.async.wait_group 1;" ::: "memory");
        } else {
            asm volatile("cp.async.wait_group 0;" ::: "memory");
        }
        __syncthreads();

        const uint32_t* As = (const uint32_t*)(smem + (size_t)s * STAGE_FLOATS);
        const uint32_t* Bs = As + OP_FLOATS;

        #pragma unroll
        for (int kp = 0; kp < 32; kp += 8) {
            uint32_t af[4][4], bf[4][2];
            #pragma unroll
            for (int mt = 0; mt < 4; mt++) {
                int r0 = wm + mt * 16 + lr;
                int cc = kp + lc;
                af[mt][0] = As[r0 * PADF + cc];
                af[mt][1] = As[(r0 + 8) * PADF + cc];
                af[mt][2] = As[r0 * PADF + cc + 4];
                af[mt][3] = As[(r0 + 8) * PADF + cc + 4];
            }
            #pragma unroll
            for (int nt = 0; nt < 4; nt++) {
                int n0 = wn + nt * 8 + lr;
                int kk = kp + lc;
                bf[nt][0] = Bs[n0 * PADF + kk];
                bf[nt][1] = Bs[n0 * PADF + kk + 4];
            }
            #pragma unroll
            for (int mt = 0; mt < 4; mt++)
                #pragma unroll
                for (int nt = 0; nt < 4; nt++)
                    mma_tf32(acc[mt][nt], af[mt], bf[nt]);
        }
        __syncthreads();
    }

    #pragma unroll
    for (int mt = 0; mt < 4; mt++) {
        #pragma unroll
        for (int nt = 0; nt < 4; nt++) {
            int gr = rowBlk + wm + mt * 16 + lr;
            int gc = colBlk + wn + nt * 8 + 2 * lc;
            float bv0 = bias[gc], bv1 = bias[gc + 1];
            float2 v0 = make_float2(acc[mt][nt][0] + bv0, acc[mt][nt][1] + bv1);
            float2 v1 = make_float2(acc[mt][nt][2] + bv0, acc[mt][nt][3] + bv1);
            *(float2*)&C[(size_t)gr * HID + gc]       = v0;
            *(float2*)&C[(size_t)(gr + 8) * HID + gc] = v1;
        }
    }
}

// ==================== weight transpose + tf32 round ====================
__global__ void transpose_cvt(const float* __restrict__ W, float* __restrict__ Wt) {
    __shared__ float tile[32][33];
    int n0 = blockIdx.x * 32, k0 = blockIdx.y * 32;
    int tx = threadIdx.x, ty = threadIdx.y;
    #pragma unroll
    for (int j = 0; j < 4; j++)
        tile[ty + j * 8][tx] = W[(size_t)(k0 + ty + j * 8) * HID + (n0 + tx)];
    __syncthreads();
    #pragma unroll
    for (int j = 0; j < 4; j++) {
        uint32_t u = f2tf32(tile[tx][ty + j * 8]);
        Wt[(size_t)(n0 + ty + j * 8) * HID + (k0 + tx)] = __uint_as_float(u);
    }
}

// ==================== CSR build ====================
__global__ void csr_hist(const int* __restrict__ dst, int* __restrict__ degi) {
    int e = blockIdx.x * blockDim.x + threadIdx.x;
    if (e < Ee) atomicAdd(&degi[dst[e]], 1);
}

// single block of 1024 threads, 16 elements each
__global__ void csr_scan(const int* __restrict__ degi, int* __restrict__ rowptr) {
    __shared__ int part[1024];
    int t = threadIdx.x;
    int base = t * 16;
    int loc[16];
    int s = 0;
    #pragma unroll
    for (int i = 0; i < 16; i++) { loc[i] = s; s += degi[base + i]; }
    part[t] = s;
    __syncthreads();
    for (int off = 1; off < 1024; off <<= 1) {
        int v = (t >= off) ? part[t - off] : 0;
        __syncthreads();
        part[t] += v;
        __syncthreads();
    }
    int pre = (t == 0) ? 0 : part[t - 1];
    #pragma unroll
    for (int i = 0; i < 16; i++) rowptr[base + i] = pre + loc[i];
    if (t == 1023) rowptr[Nn] = part[1023];
}

__global__ void csr_fill(const int* __restrict__ src, const int* __restrict__ dst,
                         const int* __restrict__ rowptr, int* __restrict__ cur,
                         int* __restrict__ col) {
    int e = blockIdx.x * blockDim.x + threadIdx.x;
    if (e >= Ee) return;
    int d = dst[e];
    int p = atomicAdd(&cur[d], 1);
    col[rowptr[d] + p] = src[e];
}

// ==================== gather-based neighbor mean ====================
// grid: Nn blocks; block: T threads. nm[r,f] = mean_{j in N(r)} x[col[j], f]
__global__ void gather_mean(const float* __restrict__ x, const int* __restrict__ rowptr,
                            const int* __restrict__ col, float* __restrict__ nm,
                            int F, int do_cvt) {
    int r = blockIdx.x;
    int beg = rowptr[r], end = rowptr[r + 1];
    float inv = (end > beg) ? 1.0f / (float)(end - beg) : 0.0f;
    for (int f = threadIdx.x; f < F; f += blockDim.x) {
        float acc = 0.0f;
        for (int j = beg; j < end; j++)
            acc += x[(size_t)col[j] * F + f];
        float v = acc * inv;
        if (do_cvt) v = __uint_as_float(f2tf32(v));
        nm[(size_t)r * F + f] = v;
    }
}

// ---------------- fp32 SGEMM (layer 1 + MLP head) ----------------
#define BM 128
#define BN 128
#define BK 16
#define TM 8
#define TN 8

__global__ __launch_bounds__(256, 2)
void sgemm_dual(const float* __restrict__ A1, const float* __restrict__ W1,
                const float* __restrict__ A2, const float* __restrict__ W2,
                const float* __restrict__ bias, float* __restrict__ C,
                int M, int Nc, int K, int do_lrelu) {
    __shared__ float As[BK][BM + 4];
    __shared__ float Bs[BK][BN];
    int tid = threadIdx.x;
    int block_row = blockIdx.y * BM;
    int block_col = blockIdx.x * BN;
    int tr = tid / (BN / TN);
    int tc = tid % (BN / TN);

    float acc[TM][TN];
    #pragma unroll
    for (int i = 0; i < TM; i++)
        #pragma unroll
        for (int j = 0; j < TN; j++) acc[i][j] = 0.0f;

    int nsrc = (A2 != nullptr) ? 2 : 1;
    for (int s = 0; s < nsrc; s++) {
        const float* A = s ? A2 : A1;
        const float* W = s ? W2 : W1;
        for (int k0 = 0; k0 < K; k0 += BK) {
            #pragma unroll
            for (int i = tid; i < BM * BK; i += 256) {
                int m = i / BK, k = i % BK;
                int gr = block_row + m, gk = k0 + k;
                As[k][m] = (gr < M && gk < K) ? A[(size_t)gr * K + gk] : 0.0f;
            }
            #pragma unroll
            for (int i = tid; i < BK * BN; i += 256) {
                int k = i / BN, n = i % BN;
                int gk = k0 + k, gc = block_col + n;
                Bs[k][n] = (gk < K && gc < Nc) ? W[(size_t)gk * Nc + gc] : 0.0f;
            }
            __syncthreads();
            #pragma unroll
            for (int k = 0; k < BK; k++) {
                float ra[TM], rb[TN];
                #pragma unroll
                for (int i = 0; i < TM; i++) ra[i] = As[k][tr * TM + i];
                #pragma unroll
                for (int j = 0; j < TN; j++) rb[j] = Bs[k][tc * TN + j];
                #pragma unroll
                for (int i = 0; i < TM; i++)
                    #pragma unroll
                    for (int j = 0; j < TN; j++)
                        acc[i][j] += ra[i] * rb[j];
            }
            __syncthreads();
        }
    }
    #pragma unroll
    for (int i = 0; i < TM; i++) {
        int gr = block_row + tr * TM + i;
        if (gr >= M) continue;
        #pragma unroll
        for (int j = 0; j < TN; j++) {
            int gc = block_col + tc * TN + j;
            if (gc >= Nc) continue;
            float v = acc[i][j] + (bias ? bias[gc] : 0.0f);
            if (do_lrelu) v = (v > 0.0f) ? v : SLOPE * v;
            C[(size_t)gr * Nc + gc] = v;
        }
    }
}

// ---------------- BN stats ----------------
__global__ void bn_stats(const float* __restrict__ X,
                         const float* __restrict__ gamma, const float* __restrict__ beta,
                         float* __restrict__ scale, float* __restrict__ shift,
                         int M, int C) {
    int lane = threadIdx.x & 31;
    int rg   = threadIdx.x >> 5;
    int col  = blockIdx.x * 32 + lane;
    float s = 0.0f, s2 = 0.0f;
    if (col < C) {
        for (int r = rg; r < M; r += 8) {
            float v = X[(size_t)r * C + col];
            s += v; s2 += v * v;
        }
    }
    __shared__ float sh[8][32], sh2[8][32];
    sh[rg][lane] = s; sh2[rg][lane] = s2;
    __syncthreads();
    if (rg == 0 && col < C) {
        #pragma unroll
        for (int i = 1; i < 8; i++) { s += sh[i][lane]; s2 += sh2[i][lane]; }
        float mu  = s / (float)M;
        float var = s2 / (float)M - mu * mu;
        float sc  = gamma[col] * rsqrtf(var + EPS);
        scale[col] = sc;
        shift[col] = beta[col] - mu * sc;
    }
}

// BN apply + leaky relu, optionally tf32-round result
__global__ void bn_apply(const float* __restrict__ X, float* __restrict__ Y,
                         const float* __restrict__ scale, const float* __restrict__ shift,
                         int C, int do_cvt) {
    int row = blockIdx.y;
    int c = blockIdx.x * blockDim.x + threadIdx.x;
    if (c >= C) return;
    float v = X[(size_t)row * C + c] * scale[c] + shift[c];
    v = (v > 0.0f) ? v : SLOPE * v;
    if (do_cvt) v = __uint_as_float(f2tf32(v));
    Y[(size_t)row * C + c] = v;
}

// ---------------- pooling (graph_id sorted -> boundary reduce) ----------------
__global__ void graph_bounds(const int* __restrict__ gid, int* __restrict__ gstart) {
    int g = threadIdx.x;
    if (g > Gg) return;
    int lo = 0, hi = Nn;
    while (lo < hi) {
        int mid = (lo + hi) >> 1;
        if (gid[mid] < g) lo = mid + 1; else hi = mid;
    }
    gstart[g] = lo;
}

// grid: (HID/256, G)
__global__ void pool_seg(const float* __restrict__ x, const int* __restrict__ gstart,
                         float* __restrict__ hg) {
    int g = blockIdx.y;
    int f = blockIdx.x * blockDim.x + threadIdx.x;
    int beg = gstart[g], end = gstart[g + 1];
    float acc = 0.0f;
    for (int r = beg; r < end; r++)
        acc += x[(size_t)r * HID + f];
    float c = (float)(end - beg);
    hg[(size_t)g * HID + f] = acc / fmaxf(c, 1.0f);
}

// ---------------- tiny final GEMM (fc3) ----------------
__global__ void head_gemm(const float* __restrict__ X, const float* __restrict__ W,
                          const float* __restrict__ b, float* __restrict__ Y,
                          int K, int Nc, int do_lrelu) {
    extern __shared__ float xs[];
    int r = blockIdx.y;
    for (int i = threadIdx.x; i < K; i += blockDim.x) xs[i] = X[(size_t)r * K + i];
    __syncthreads();
    int c = blockIdx.x * blockDim.x + threadIdx.x;
    if (c >= Nc) return;
    float acc = 0.0f;
    for (int k = 0; k < K; k++) acc += xs[k] * W[(size_t)k * Nc + c];
    acc += b[c];
    if (do_lrelu) acc = (acc > 0.0f) ? acc : SLOPE * acc;
    Y[(size_t)r * Nc + c] = acc;
}

// ==================== launch ====================
extern "C" void kernel_launch(void* const* d_in, const int* in_sizes, int n_in,
                              void* d_out, int out_size) {
    (void)in_sizes; (void)n_in; (void)out_size;
    const float* h     = (const float*)d_in[0];
    const int*   src   = (const int*)  d_in[1];
    const int*   dst   = (const int*)  d_in[2];
    const int*   gid   = (const int*)  d_in[3];
    const float* Ws1   = (const float*)d_in[4];
    const float* Wn1   = (const float*)d_in[5];
    const float* b1    = (const float*)d_in[6];
    const float* Ws2   = (const float*)d_in[7];
    const float* Wn2   = (const float*)d_in[8];
    const float* b2    = (const float*)d_in[9];
    const float* Ws3   = (const float*)d_in[10];
    const float* Wn3   = (const float*)d_in[11];
    const float* b3    = (const float*)d_in[12];
    const float* g1    = (const float*)d_in[13];
    const float* be1   = (const float*)d_in[14];
    const float* g2    = (const float*)d_in[15];
    const float* be2   = (const float*)d_in[16];
    const float* g3    = (const float*)d_in[17];
    const float* be3   = (const float*)d_in[18];
    const float* fc1_w = (const float*)d_in[19];
    const float* fc1_b = (const float*)d_in[20];
    const float* fc2_w = (const float*)d_in[21];
    const float* fc2_b = (const float*)d_in[22];
    const float* fc3_w = (const float*)d_in[23];
    const float* fc3_b = (const float*)d_in[24];
    float* out = (float*)d_out;

    float *nm, *x, *y, *scale, *shift, *hg, *t1, *t2;
    float *wt2s, *wt2n, *wt3s, *wt3n;
    int *degi, *cur, *rowptr, *col, *gstart;
    cudaGetSymbolAddress((void**)&nm,    g_nm);
    cudaGetSymbolAddress((void**)&x,     g_x);
    cudaGetSymbolAddress((void**)&y,     g_y);
    cudaGetSymbolAddress((void**)&scale, g_scale);
    cudaGetSymbolAddress((void**)&shift, g_shift);
    cudaGetSymbolAddress((void**)&hg,    g_hg);
    cudaGetSymbolAddress((void**)&t1,    g_t1);
    cudaGetSymbolAddress((void**)&t2,    g_t2);
    cudaGetSymbolAddress((void**)&wt2s,  g_wt2s);
    cudaGetSymbolAddress((void**)&wt2n,  g_wt2n);
    cudaGetSymbolAddress((void**)&wt3s,  g_wt3s);
    cudaGetSymbolAddress((void**)&wt3n,  g_wt3n);
    cudaGetSymbolAddress((void**)&degi,   g_degi);
    cudaGetSymbolAddress((void**)&cur,    g_cur);
    cudaGetSymbolAddress((void**)&rowptr, g_rowptr);
    cudaGetSymbolAddress((void**)&col,    g_col);
    cudaGetSymbolAddress((void**)&gstart, g_gstart);

    cudaFuncSetAttribute(tc_gemm_dual, cudaFuncAttributeMaxDynamicSharedMemorySize, TCG_SMEM_BYTES);

    cudaStream_t s = 0;

    // weight transposes (+ tf32 rounding)
    dim3 tgrid(HID / 32, HID / 32), tblk(32, 8);
    transpose_cvt<<<tgrid, tblk, 0, s>>>(Ws2, wt2s);
    transpose_cvt<<<tgrid, tblk, 0, s>>>(Wn2, wt2n);
    transpose_cvt<<<tgrid, tblk, 0, s>>>(Ws3, wt3s);
    transpose_cvt<<<tgrid, tblk, 0, s>>>(Wn3, wt3n);

    // CSR build + graph boundaries
    cudaMemsetAsync(degi, 0, Nn * sizeof(int), s);
    cudaMemsetAsync(cur,  0, Nn * sizeof(int), s);
    csr_hist<<<Ee / 256, 256, 0, s>>>(dst, degi);
    csr_scan<<<1, 1024, 0, s>>>(degi, rowptr);
    csr_fill<<<Ee / 256, 256, 0, s>>>(src, dst, rowptr, cur, col);
    graph_bounds<<<1, 128, 0, s>>>(gid, gstart);

    dim3 tc_grid(HID / 128, Nn / 128);

    // ---- Layer 1 (K = 63, fp32 SGEMM) ----
    gather_mean<<<Nn, 64, 0, s>>>(h, rowptr, col, nm, INF, 0);
    sgemm_dual<<<dim3(HID / BN, Nn / BM), 256, 0, s>>>(h, Ws1, nm, Wn1, b1, y, Nn, HID, INF, 0);
    bn_stats<<<HID / 32, 256, 0, s>>>(y, g1, be1, scale, shift, Nn, HID);
    bn_apply<<<dim3(HID / 256, Nn), 256, 0, s>>>(y, x, scale, shift, HID, 1);

    // ---- Layer 2 (tf32 mma.sync) ----
    gather_mean<<<Nn, 256, 0, s>>>(x, rowptr, col, nm, HID, 1);
    tc_gemm_dual<<<tc_grid, 256, TCG_SMEM_BYTES, s>>>(x, wt2s, nm, wt2n, b2, y);
    bn_stats<<<HID / 32, 256, 0, s>>>(y, g2, be2, scale, shift, Nn, HID);
    bn_apply<<<dim3(HID / 256, Nn), 256, 0, s>>>(y, x, scale, shift, HID, 1);

    // ---- Layer 3 (tf32 mma.sync) ----
    gather_mean<<<Nn, 256, 0, s>>>(x, rowptr, col, nm, HID, 1);
    tc_gemm_dual<<<tc_grid, 256, TCG_SMEM_BYTES, s>>>(x, wt3s, nm, wt3n, b3, y);
    bn_stats<<<HID / 32, 256, 0, s>>>(y, g3, be3, scale, shift, Nn, HID);
    bn_apply<<<dim3(HID / 256, Nn), 256, 0, s>>>(y, x, scale, shift, HID, 0);

    // ---- Average pooling over graphs (no atomics) ----
    pool_seg<<<dim3(HID / 256, Gg), 256, 0, s>>>(x, gstart, hg);

    // ---- MLP head: tiled GEMMs (weights read once) ----
    sgemm_dual<<<dim3(HID / BN, 1), 256, 0, s>>>(hg, fc1_w, nullptr, nullptr, fc1_b, t1,
                                                 Gg, HID, HID, 1);
    sgemm_dual<<<dim3(MIDD / BN, 1), 256, 0, s>>>(t1, fc2_w, nullptr, nullptr, fc2_b, t2,
                                                  Gg, MIDD, HID, 1);
    head_gemm<<<dim3(1, Gg), 128, MIDD * sizeof(float), s>>>(t2, fc3_w, fc3_b, out, MIDD, NCLS, 0);
}

// round 5
// speedup vs baseline: 1.3508x; 1.3508x over previous
#include <cuda_runtime.h>
#include <cstdint>
#include <math.h>

// Problem constants
#define Nn   16384
#define Ee   65536
#define Gg   64
#define INF  63
#define HID  2048
#define MIDD 1024
#define NCLS 18
#define SLOPE 0.01f
#define EPS   1e-5f

// ---------------- scratch (device globals; no allocation allowed) ----------------
__device__ float g_nm[(size_t)Nn * HID];   // neighbor mean buffer
__device__ float g_x [(size_t)Nn * HID];   // current activations
__device__ float g_y [(size_t)Nn * HID];   // GEMM output
__device__ float g_deg[Nn];
__device__ float g_scale[HID];
__device__ float g_shift[HID];
__device__ float g_hg[Gg * HID];
__device__ float g_t1[Gg * HID];
__device__ float g_t2[Gg * MIDD];
__device__ int   g_gstart[Gg + 1];
// transposed + tf32-rounded weights [N rows, K cols] (K-major)
__device__ float g_wt2s[(size_t)HID * HID];
__device__ float g_wt2n[(size_t)HID * HID];
__device__ float g_wt3s[(size_t)HID * HID];
__device__ float g_wt3n[(size_t)HID * HID];

// ==================== helpers ====================
__device__ __forceinline__ uint32_t smem_u32(const void* p) {
    uint32_t a;
    asm("{ .reg .u64 t; cvta.to.shared.u64 t, %1; cvt.u32.u64 %0, t; }" : "=r"(a) : "l"(p));
    return a;
}
__device__ __forceinline__ uint32_t f2tf32(float v) {
    uint32_t r; asm("cvt.rna.tf32.f32 %0, %1;" : "=r"(r) : "f"(v)); return r;
}
__device__ __forceinline__ void cp_async16(uint32_t dst, const void* src) {
    asm volatile("cp.async.cg.shared.global [%0], [%1], 16;" :: "r"(dst), "l"(src) : "memory");
}
__device__ __forceinline__ void cp_commit() {
    asm volatile("cp.async.commit_group;" ::: "memory");
}
__device__ __forceinline__ void mma_tf32(float* d, const uint32_t* a, const uint32_t* b) {
    asm volatile(
        "mma.sync.aligned.m16n8k8.row.col.f32.tf32.tf32.f32 "
        "{%0,%1,%2,%3}, {%4,%5,%6,%7}, {%8,%9}, {%0,%1,%2,%3};"
        : "+f"(d[0]), "+f"(d[1]), "+f"(d[2]), "+f"(d[3])
        : "r"(a[0]), "r"(a[1]), "r"(a[2]), "r"(a[3]), "r"(b[0]), "r"(b[1]));
}

// ==================== tf32 mma.sync dual-source GEMM ====================
// C[M=16384, N=2048] = A1@B1^T + A2@B2^T + bias.  K = 2048 per source.
#define PADF 36
#define OP_FLOATS (128 * PADF)
#define STAGE_FLOATS (2 * OP_FLOATS)
#define TCG_SMEM_BYTES (2 * STAGE_FLOATS * 4)     // 73728 B

__global__ void __launch_bounds__(256, 2)
tc_gemm_dual(const float* __restrict__ A1, const float* __restrict__ B1,
             const float* __restrict__ A2, const float* __restrict__ B2,
             const float* __restrict__ bias, float* __restrict__ C) {
    extern __shared__ __align__(16) float smem[];
    uint32_t sb = smem_u32(smem);
    const int tid  = threadIdx.x;
    const int wid  = tid >> 5;
    const int lane = tid & 31;
    const int rowBlk = blockIdx.y * 128;
    const int colBlk = blockIdx.x * 128;
    const int wm = (wid & 1) * 64;
    const int wn = (wid >> 1) * 32;
    const int lr = lane >> 2;
    const int lc = lane & 3;

    float acc[4][4][4];
    #pragma unroll
    for (int i = 0; i < 4; i++)
        #pragma unroll
        for (int j = 0; j < 4; j++)
            #pragma unroll
            for (int k = 0; k < 4; k++) acc[i][j][k] = 0.0f;

    const int NC  = HID / 32;
    const int TOT = 2 * NC;

    {
        #pragma unroll
        for (int i = 0; i < 4; i++) {
            int t = tid + i * 256;
            int r = t >> 3, sg = t & 7;
            uint32_t off = (uint32_t)r * (PADF * 4) + (uint32_t)sg * 16;
            cp_async16(sb + off, A1 + (size_t)(rowBlk + r) * HID + sg * 4);
            cp_async16(sb + OP_FLOATS * 4 + off, B1 + (size_t)(colBlk + r) * HID + sg * 4);
        }
        cp_commit();
    }

    for (int c = 0; c < TOT; c++) {
        int s = c & 1;
        if (c + 1 < TOT) {
            int n2 = c + 1;
            const float* A = (n2 < NC) ? A1 : A2;
            const float* B = (n2 < NC) ? B1 : B2;
            int k0 = (n2 & (NC - 1)) * 32;
            uint32_t base = sb + (uint32_t)(s ^ 1) * (STAGE_FLOATS * 4);
            #pragma unroll
            for (int i = 0; i < 4; i++) {
                int t = tid + i * 256;
                int r = t >> 3, sg = t & 7;
                uint32_t off = (uint32_t)r * (PADF * 4) + (uint32_t)sg * 16;
                cp_async16(base + off, A + (size_t)(rowBlk + r) * HID + k0 + sg * 4);
                cp_async16(base + OP_FLOATS * 4 + off, B + (size_t)(colBlk + r) * HID + k0 + sg * 4);
            }
            cp_commit();
            asm volatile("cp.async.wait_group 1;" ::: "memory");
        } else {
            asm volatile("cp.async.wait_group 0;" ::: "memory");
        }
        __syncthreads();

        const uint32_t* As = (const uint32_t*)(smem + (size_t)s * STAGE_FLOATS);
        const uint32_t* Bs = As + OP_FLOATS;

        #pragma unroll
        for (int kp = 0; kp < 32; kp += 8) {
            uint32_t af[4][4], bf[4][2];
            #pragma unroll
            for (int mt = 0; mt < 4; mt++) {
                int r0 = wm + mt * 16 + lr;
                int cc = kp + lc;
                af[mt][0] = As[r0 * PADF + cc];
                af[mt][1] = As[(r0 + 8) * PADF + cc];
                af[mt][2] = As[r0 * PADF + cc + 4];
                af[mt][3] = As[(r0 + 8) * PADF + cc + 4];
            }
            #pragma unroll
            for (int nt = 0; nt < 4; nt++) {
                int n0 = wn + nt * 8 + lr;
                int kk = kp + lc;
                bf[nt][0] = Bs[n0 * PADF + kk];
                bf[nt][1] = Bs[n0 * PADF + kk + 4];
            }
            #pragma unroll
            for (int mt = 0; mt < 4; mt++)
                #pragma unroll
                for (int nt = 0; nt < 4; nt++)
                    mma_tf32(acc[mt][nt], af[mt], bf[nt]);
        }
        __syncthreads();
    }

    #pragma unroll
    for (int mt = 0; mt < 4; mt++) {
        #pragma unroll
        for (int nt = 0; nt < 4; nt++) {
            int gr = rowBlk + wm + mt * 16 + lr;
            int gc = colBlk + wn + nt * 8 + 2 * lc;
            float bv0 = bias[gc], bv1 = bias[gc + 1];
            float2 v0 = make_float2(acc[mt][nt][0] + bv0, acc[mt][nt][1] + bv1);
            float2 v1 = make_float2(acc[mt][nt][2] + bv0, acc[mt][nt][3] + bv1);
            *(float2*)&C[(size_t)gr * HID + gc]       = v0;
            *(float2*)&C[(size_t)(gr + 8) * HID + gc] = v1;
        }
    }
}

// ==================== weight transpose + tf32 round ====================
__global__ void transpose_cvt(const float* __restrict__ W, float* __restrict__ Wt) {
    __shared__ float tile[32][33];
    int n0 = blockIdx.x * 32, k0 = blockIdx.y * 32;
    int tx = threadIdx.x, ty = threadIdx.y;
    #pragma unroll
    for (int j = 0; j < 4; j++)
        tile[ty + j * 8][tx] = W[(size_t)(k0 + ty + j * 8) * HID + (n0 + tx)];
    __syncthreads();
    #pragma unroll
    for (int j = 0; j < 4; j++) {
        uint32_t u = f2tf32(tile[tx][ty + j * 8]);
        Wt[(size_t)(n0 + ty + j * 8) * HID + (k0 + tx)] = __uint_as_float(u);
    }
}

// ==================== graph / elementwise kernels ====================
__global__ void deg_kernel(const int* __restrict__ dst, float* __restrict__ deg) {
    int i = blockIdx.x * blockDim.x + threadIdx.x;
    if (i < Ee) atomicAdd(&deg[dst[i]], 1.0f);
}

__global__ void scatter_add(const float* __restrict__ x, const int* __restrict__ src,
                            const int* __restrict__ dst, float* __restrict__ out, int F) {
    int e = blockIdx.x;
    int f = blockIdx.y * blockDim.x + threadIdx.x;
    if (f >= F) return;
    int s = src[e], d = dst[e];
    atomicAdd(&out[(size_t)d * F + f], x[(size_t)s * F + f]);
}

// divide rows by max(deg,1); optionally tf32-round the result
__global__ void row_div(float* __restrict__ nm, const float* __restrict__ deg, int F, int do_cvt) {
    int row = blockIdx.y;
    int f = blockIdx.x * blockDim.x + threadIdx.x;
    if (f >= F) return;
    float d = deg[row];
    float v = nm[(size_t)row * F + f] * (1.0f / fmaxf(d, 1.0f));
    if (do_cvt) v = __uint_as_float(f2tf32(v));
    nm[(size_t)row * F + f] = v;
}

// ---------------- fp32 SGEMM (layer 1 + MLP head) ----------------
#define BM 128
#define BN 128
#define BK 16
#define TM 8
#define TN 8

__global__ __launch_bounds__(256, 2)
void sgemm_dual(const float* __restrict__ A1, const float* __restrict__ W1,
                const float* __restrict__ A2, const float* __restrict__ W2,
                const float* __restrict__ bias, float* __restrict__ C,
                int M, int Nc, int K, int do_lrelu) {
    __shared__ float As[BK][BM + 4];
    __shared__ float Bs[BK][BN];
    int tid = threadIdx.x;
    int block_row = blockIdx.y * BM;
    int block_col = blockIdx.x * BN;
    int tr = tid / (BN / TN);
    int tc = tid % (BN / TN);

    float acc[TM][TN];
    #pragma unroll
    for (int i = 0; i < TM; i++)
        #pragma unroll
        for (int j = 0; j < TN; j++) acc[i][j] = 0.0f;

    int nsrc = (A2 != nullptr) ? 2 : 1;
    for (int s = 0; s < nsrc; s++) {
        const float* A = s ? A2 : A1;
        const float* W = s ? W2 : W1;
        for (int k0 = 0; k0 < K; k0 += BK) {
            #pragma unroll
            for (int i = tid; i < BM * BK; i += 256) {
                int m = i / BK, k = i % BK;
                int gr = block_row + m, gk = k0 + k;
                As[k][m] = (gr < M && gk < K) ? A[(size_t)gr * K + gk] : 0.0f;
            }
            #pragma unroll
            for (int i = tid; i < BK * BN; i += 256) {
                int k = i / BN, n = i % BN;
                int gk = k0 + k, gc = block_col + n;
                Bs[k][n] = (gk < K && gc < Nc) ? W[(size_t)gk * Nc + gc] : 0.0f;
            }
            __syncthreads();
            #pragma unroll
            for (int k = 0; k < BK; k++) {
                float ra[TM], rb[TN];
                #pragma unroll
                for (int i = 0; i < TM; i++) ra[i] = As[k][tr * TM + i];
                #pragma unroll
                for (int j = 0; j < TN; j++) rb[j] = Bs[k][tc * TN + j];
                #pragma unroll
                for (int i = 0; i < TM; i++)
                    #pragma unroll
                    for (int j = 0; j < TN; j++)
                        acc[i][j] += ra[i] * rb[j];
            }
            __syncthreads();
        }
    }
    #pragma unroll
    for (int i = 0; i < TM; i++) {
        int gr = block_row + tr * TM + i;
        if (gr >= M) continue;
        #pragma unroll
        for (int j = 0; j < TN; j++) {
            int gc = block_col + tc * TN + j;
            if (gc >= Nc) continue;
            float v = acc[i][j] + (bias ? bias[gc] : 0.0f);
            if (do_lrelu) v = (v > 0.0f) ? v : SLOPE * v;
            C[(size_t)gr * Nc + gc] = v;
        }
    }
}

// ---------------- BN stats ----------------
__global__ void bn_stats(const float* __restrict__ X,
                         const float* __restrict__ gamma, const float* __restrict__ beta,
                         float* __restrict__ scale, float* __restrict__ shift,
                         int M, int C) {
    int lane = threadIdx.x & 31;
    int rg   = threadIdx.x >> 5;
    int col  = blockIdx.x * 32 + lane;
    float s = 0.0f, s2 = 0.0f;
    if (col < C) {
        for (int r = rg; r < M; r += 8) {
            float v = X[(size_t)r * C + col];
            s += v; s2 += v * v;
        }
    }
    __shared__ float sh[8][32], sh2[8][32];
    sh[rg][lane] = s; sh2[rg][lane] = s2;
    __syncthreads();
    if (rg == 0 && col < C) {
        #pragma unroll
        for (int i = 1; i < 8; i++) { s += sh[i][lane]; s2 += sh2[i][lane]; }
        float mu  = s / (float)M;
        float var = s2 / (float)M - mu * mu;
        float sc  = gamma[col] * rsqrtf(var + EPS);
        scale[col] = sc;
        shift[col] = beta[col] - mu * sc;
    }
}

// BN apply + leaky relu, optionally tf32-round result
__global__ void bn_apply(const float* __restrict__ X, float* __restrict__ Y,
                         const float* __restrict__ scale, const float* __restrict__ shift,
                         int C, int do_cvt) {
    int row = blockIdx.y;
    int c = blockIdx.x * blockDim.x + threadIdx.x;
    if (c >= C) return;
    float v = X[(size_t)row * C + c] * scale[c] + shift[c];
    v = (v > 0.0f) ? v : SLOPE * v;
    if (do_cvt) v = __uint_as_float(f2tf32(v));
    Y[(size_t)row * C + c] = v;
}

// ---------------- pooling (graph_id sorted -> boundary reduce) ----------------
__global__ void graph_bounds(const int* __restrict__ gid, int* __restrict__ gstart) {
    int g = threadIdx.x;
    if (g > Gg) return;
    int lo = 0, hi = Nn;
    while (lo < hi) {
        int mid = (lo + hi) >> 1;
        if (gid[mid] < g) lo = mid + 1; else hi = mid;
    }
    gstart[g] = lo;
}

// grid: (HID/256, G)
__global__ void pool_seg(const float* __restrict__ x, const int* __restrict__ gstart,
                         float* __restrict__ hg) {
    int g = blockIdx.y;
    int f = blockIdx.x * blockDim.x + threadIdx.x;
    int beg = gstart[g], end = gstart[g + 1];
    float acc = 0.0f;
    for (int r = beg; r < end; r++)
        acc += x[(size_t)r * HID + f];
    float c = (float)(end - beg);
    hg[(size_t)g * HID + f] = acc / fmaxf(c, 1.0f);
}

// ---------------- tiny final GEMM (fc3) ----------------
__global__ void head_gemm(const float* __restrict__ X, const float* __restrict__ W,
                          const float* __restrict__ b, float* __restrict__ Y,
                          int K, int Nc, int do_lrelu) {
    extern __shared__ float xs[];
    int r = blockIdx.y;
    for (int i = threadIdx.x; i < K; i += blockDim.x) xs[i] = X[(size_t)r * K + i];
    __syncthreads();
    int c = blockIdx.x * blockDim.x + threadIdx.x;
    if (c >= Nc) return;
    float acc = 0.0f;
    for (int k = 0; k < K; k++) acc += xs[k] * W[(size_t)k * Nc + c];
    acc += b[c];
    if (do_lrelu) acc = (acc > 0.0f) ? acc : SLOPE * acc;
    Y[(size_t)r * Nc + c] = acc;
}

// ==================== launch ====================
extern "C" void kernel_launch(void* const* d_in, const int* in_sizes, int n_in,
                              void* d_out, int out_size) {
    (void)in_sizes; (void)n_in; (void)out_size;
    const float* h     = (const float*)d_in[0];
    const int*   src   = (const int*)  d_in[1];
    const int*   dst   = (const int*)  d_in[2];
    const int*   gid   = (const int*)  d_in[3];
    const float* Ws1   = (const float*)d_in[4];
    const float* Wn1   = (const float*)d_in[5];
    const float* b1    = (const float*)d_in[6];
    const float* Ws2   = (const float*)d_in[7];
    const float* Wn2   = (const float*)d_in[8];
    const float* b2    = (const float*)d_in[9];
    const float* Ws3   = (const float*)d_in[10];
    const float* Wn3   = (const float*)d_in[11];
    const float* b3    = (const float*)d_in[12];
    const float* g1    = (const float*)d_in[13];
    const float* be1   = (const float*)d_in[14];
    const float* g2    = (const float*)d_in[15];
    const float* be2   = (const float*)d_in[16];
    const float* g3    = (const float*)d_in[17];
    const float* be3   = (const float*)d_in[18];
    const float* fc1_w = (const float*)d_in[19];
    const float* fc1_b = (const float*)d_in[20];
    const float* fc2_w = (const float*)d_in[21];
    const float* fc2_b = (const float*)d_in[22];
    const float* fc3_w = (const float*)d_in[23];
    const float* fc3_b = (const float*)d_in[24];
    float* out = (float*)d_out;

    float *nm, *x, *y, *deg, *scale, *shift, *hg, *t1, *t2;
    float *wt2s, *wt2n, *wt3s, *wt3n;
    int *gstart;
    cudaGetSymbolAddress((void**)&nm,    g_nm);
    cudaGetSymbolAddress((void**)&x,     g_x);
    cudaGetSymbolAddress((void**)&y,     g_y);
    cudaGetSymbolAddress((void**)&deg,   g_deg);
    cudaGetSymbolAddress((void**)&scale, g_scale);
    cudaGetSymbolAddress((void**)&shift, g_shift);
    cudaGetSymbolAddress((void**)&hg,    g_hg);
    cudaGetSymbolAddress((void**)&t1,    g_t1);
    cudaGetSymbolAddress((void**)&t2,    g_t2);
    cudaGetSymbolAddress((void**)&wt2s,  g_wt2s);
    cudaGetSymbolAddress((void**)&wt2n,  g_wt2n);
    cudaGetSymbolAddress((void**)&wt3s,  g_wt3s);
    cudaGetSymbolAddress((void**)&wt3n,  g_wt3n);
    cudaGetSymbolAddress((void**)&gstart, g_gstart);

    cudaFuncSetAttribute(tc_gemm_dual, cudaFuncAttributeMaxDynamicSharedMemorySize, TCG_SMEM_BYTES);

    cudaStream_t s = 0;

    // weight transposes (+ tf32 rounding)
    dim3 tgrid(HID / 32, HID / 32), tblk(32, 8);
    transpose_cvt<<<tgrid, tblk, 0, s>>>(Ws2, wt2s);
    transpose_cvt<<<tgrid, tblk, 0, s>>>(Wn2, wt2n);
    transpose_cvt<<<tgrid, tblk, 0, s>>>(Ws3, wt3s);
    transpose_cvt<<<tgrid, tblk, 0, s>>>(Wn3, wt3n);

    // degrees + graph boundaries
    cudaMemsetAsync(deg, 0, Nn * sizeof(float), s);
    deg_kernel<<<Ee / 256, 256, 0, s>>>(dst, deg);
    graph_bounds<<<1, 128, 0, s>>>(gid, gstart);

    dim3 tc_grid(HID / 128, Nn / 128);

    // ---- Layer 1 (K = 63, fp32 SGEMM) ----
    cudaMemsetAsync(nm, 0, (size_t)Nn * INF * sizeof(float), s);
    scatter_add<<<dim3(Ee, 1), 64, 0, s>>>(h, src, dst, nm, INF);
    row_div<<<dim3(1, Nn), 64, 0, s>>>(nm, deg, INF, 0);
    sgemm_dual<<<dim3(HID / BN, Nn / BM), 256, 0, s>>>(h, Ws1, nm, Wn1, b1, y, Nn, HID, INF, 0);
    bn_stats<<<HID / 32, 256, 0, s>>>(y, g1, be1, scale, shift, Nn, HID);
    bn_apply<<<dim3(HID / 256, Nn), 256, 0, s>>>(y, x, scale, shift, HID, 1);

    // ---- Layer 2 (tf32 mma.sync) ----
    cudaMemsetAsync(nm, 0, (size_t)Nn * HID * sizeof(float), s);
    scatter_add<<<dim3(Ee, HID / 256), 256, 0, s>>>(x, src, dst, nm, HID);
    row_div<<<dim3(HID / 256, Nn), 256, 0, s>>>(nm, deg, HID, 1);
    tc_gemm_dual<<<tc_grid, 256, TCG_SMEM_BYTES, s>>>(x, wt2s, nm, wt2n, b2, y);
    bn_stats<<<HID / 32, 256, 0, s>>>(y, g2, be2, scale, shift, Nn, HID);
    bn_apply<<<dim3(HID / 256, Nn), 256, 0, s>>>(y, x, scale, shift, HID, 1);

    // ---- Layer 3 (tf32 mma.sync) ----
    cudaMemsetAsync(nm, 0, (size_t)Nn * HID * sizeof(float), s);
    scatter_add<<<dim3(Ee, HID / 256), 256, 0, s>>>(x, src, dst, nm, HID);
    row_div<<<dim3(HID / 256, Nn), 256, 0, s>>>(nm, deg, HID, 1);
    tc_gemm_dual<<<tc_grid, 256, TCG_SMEM_BYTES, s>>>(x, wt3s, nm, wt3n, b3, y);
    bn_stats<<<HID / 32, 256, 0, s>>>(y, g3, be3, scale, shift, Nn, HID);
    bn_apply<<<dim3(HID / 256, Nn), 256, 0, s>>>(y, x, scale, shift, HID, 0);

    // ---- Average pooling over graphs (segmented, no atomics) ----
    pool_seg<<<dim3(HID / 256, Gg), 256, 0, s>>>(x, gstart, hg);

    // ---- MLP head: tiled GEMMs (weights read once) ----
    sgemm_dual<<<dim3(HID / BN, 1), 256, 0, s>>>(hg, fc1_w, nullptr, nullptr, fc1_b, t1,
                                                 Gg, HID, HID, 1);
    sgemm_dual<<<dim3(MIDD / BN, 1), 256, 0, s>>>(t1, fc2_w, nullptr, nullptr, fc2_b, t2,
                                                  Gg, MIDD, HID, 1);
    head_gemm<<<dim3(1, Gg), 128, MIDD * sizeof(float), s>>>(t2, fc3_w, fc3_b, out, MIDD, NCLS, 0);
}

// round 6
// speedup vs baseline: 1.4875x; 1.1012x over previous
#include <cuda_runtime.h>
#include <cstdint>
#include <math.h>

// Problem constants
#define Nn   16384
#define Ee   65536
#define Gg   64
#define INF  63
#define HID  2048
#define MIDD 1024
#define NCLS 18
#define SLOPE 0.01f
#define EPS   1e-5f

// ---------------- scratch (device globals; no allocation allowed) ----------------
__device__ float g_nm[(size_t)Nn * HID];   // neighbor mean buffer
__device__ float g_x [(size_t)Nn * HID];   // current activations
__device__ float g_y [(size_t)Nn * HID];   // GEMM output
__device__ float g_deg[Nn];
__device__ float g_scale[HID];
__device__ float g_shift[HID];
__device__ float g_hg[Gg * HID];
__device__ float g_cnt[Gg];
__device__ float g_t1[Gg * HID];
__device__ float g_t2[Gg * MIDD];
// transposed + tf32-rounded weights [N rows, K cols] (K-major)
__device__ float g_wt2s[(size_t)HID * HID];
__device__ float g_wt2n[(size_t)HID * HID];
__device__ float g_wt3s[(size_t)HID * HID];
__device__ float g_wt3n[(size_t)HID * HID];

// ==================== helpers ====================
__device__ __forceinline__ uint32_t smem_u32(const void* p) {
    uint32_t a;
    asm("{ .reg .u64 t; cvta.to.shared.u64 t, %1; cvt.u32.u64 %0, t; }" : "=r"(a) : "l"(p));
    return a;
}
__device__ __forceinline__ uint32_t f2tf32(float v) {
    uint32_t r; asm("cvt.rna.tf32.f32 %0, %1;" : "=r"(r) : "f"(v)); return r;
}
__device__ __forceinline__ void cp_async16(uint32_t dst, const void* src) {
    asm volatile("cp.async.cg.shared.global [%0], [%1], 16;" :: "r"(dst), "l"(src) : "memory");
}
__device__ __forceinline__ void cp_commit() {
    asm volatile("cp.async.commit_group;" ::: "memory");
}
__device__ __forceinline__ void mma_tf32(float* d, const uint32_t* a, const uint32_t* b) {
    asm volatile(
        "mma.sync.aligned.m16n8k8.row.col.f32.tf32.tf32.f32 "
        "{%0,%1,%2,%3}, {%4,%5,%6,%7}, {%8,%9}, {%0,%1,%2,%3};"
        : "+f"(d[0]), "+f"(d[1]), "+f"(d[2]), "+f"(d[3])
        : "r"(a[0]), "r"(a[1]), "r"(a[2]), "r"(a[3]), "r"(b[0]), "r"(b[1]));
}

// ==================== tf32 mma.sync dual-source GEMM (3-stage pipeline) ====================
// C[M=16384, N=2048] = A1@B1^T + A2@B2^T + bias.  K = 2048 per source.
#define PADF 36
#define OP_FLOATS (128 * PADF)
#define STAGE_FLOATS (2 * OP_FLOATS)
#define NSTAGE 3
#define TCG_SMEM_BYTES (NSTAGE * STAGE_FLOATS * 4)   // 110592 B

__device__ __forceinline__ void tcg_issue_chunk(uint32_t sb, int stage, int tid,
                                                const float* A, const float* B,
                                                int rowBlk, int colBlk, int k0) {
    uint32_t base = sb + (uint32_t)stage * (STAGE_FLOATS * 4);
    #pragma unroll
    for (int i = 0; i < 4; i++) {
        int t = tid + i * 256;
        int r = t >> 3, sg = t & 7;
        uint32_t off = (uint32_t)r * (PADF * 4) + (uint32_t)sg * 16;
        cp_async16(base + off, A + (size_t)(rowBlk + r) * HID + k0 + sg * 4);
        cp_async16(base + OP_FLOATS * 4 + off, B + (size_t)(colBlk + r) * HID + k0 + sg * 4);
    }
}

__global__ void __launch_bounds__(256, 2)
tc_gemm_dual(const float* __restrict__ A1, const float* __restrict__ B1,
             const float* __restrict__ A2, const float* __restrict__ B2,
             const float* __restrict__ bias, float* __restrict__ C) {
    extern __shared__ __align__(16) float smem[];
    uint32_t sb = smem_u32(smem);
    const int tid  = threadIdx.x;
    const int wid  = tid >> 5;
    const int lane = tid & 31;
    const int rowBlk = blockIdx.y * 128;
    const int colBlk = blockIdx.x * 128;
    const int wm = (wid & 1) * 64;
    const int wn = (wid >> 1) * 32;
    const int lr = lane >> 2;
    const int lc = lane & 3;

    float acc[4][4][4];
    #pragma unroll
    for (int i = 0; i < 4; i++)
        #pragma unroll
        for (int j = 0; j < 4; j++)
            #pragma unroll
            for (int k = 0; k < 4; k++) acc[i][j][k] = 0.0f;

    const int NC  = HID / 32;   // 64 chunks per source
    const int TOT = 2 * NC;     // 128

    // preload chunks 0 and 1 into stages 0, 1
    tcg_issue_chunk(sb, 0, tid, A1, B1, rowBlk, colBlk, 0);
    cp_commit();
    tcg_issue_chunk(sb, 1, tid, A1, B1, rowBlk, colBlk, 32);
    cp_commit();

    int sc = 0;  // stage of chunk c
    for (int c = 0; c < TOT; c++) {
        // prefetch chunk c+2 into stage (c+2)%3 (safe: that stage was last read
        // during iteration c-1, protected by the loop-end barrier)
        int n2 = c + 2;
        if (n2 < TOT) {
            const float* A = (n2 < NC) ? A1 : A2;
            const float* B = (n2 < NC) ? B1 : B2;
            int k0 = (n2 & (NC - 1)) * 32;
            int ps = sc + 2; if (ps >= NSTAGE) ps -= NSTAGE;
            tcg_issue_chunk(sb, ps, tid, A, B, rowBlk, colBlk, k0);
        }
        cp_commit();  // always commit (possibly empty) to keep group counting uniform
        asm volatile("cp.async.wait_group 2;" ::: "memory");
        __syncthreads();

        const uint32_t* As = (const uint32_t*)(smem + (size_t)sc * STAGE_FLOATS);
        const uint32_t* Bs = As + OP_FLOATS;

        #pragma unroll
        for (int kp = 0; kp < 32; kp += 8) {
            uint32_t af[4][4], bf[4][2];
            #pragma unroll
            for (int mt = 0; mt < 4; mt++) {
                int r0 = wm + mt * 16 + lr;
                int cc = kp + lc;
                af[mt][0] = As[r0 * PADF + cc];
                af[mt][1] = As[(r0 + 8) * PADF + cc];
                af[mt][2] = As[r0 * PADF + cc + 4];
                af[mt][3] = As[(r0 + 8) * PADF + cc + 4];
            }
            #pragma unroll
            for (int nt = 0; nt < 4; nt++) {
                int n0 = wn + nt * 8 + lr;
                int kk = kp + lc;
                bf[nt][0] = Bs[n0 * PADF + kk];
                bf[nt][1] = Bs[n0 * PADF + kk + 4];
            }
            #pragma unroll
            for (int mt = 0; mt < 4; mt++)
                #pragma unroll
                for (int nt = 0; nt < 4; nt++)
                    mma_tf32(acc[mt][nt], af[mt], bf[nt]);
        }
        __syncthreads();
        sc++; if (sc >= NSTAGE) sc = 0;
    }

    #pragma unroll
    for (int mt = 0; mt < 4; mt++) {
        #pragma unroll
        for (int nt = 0; nt < 4; nt++) {
            int gr = rowBlk + wm + mt * 16 + lr;
            int gc = colBlk + wn + nt * 8 + 2 * lc;
            float bv0 = bias[gc], bv1 = bias[gc + 1];
            float2 v0 = make_float2(acc[mt][nt][0] + bv0, acc[mt][nt][1] + bv1);
            float2 v1 = make_float2(acc[mt][nt][2] + bv0, acc[mt][nt][3] + bv1);
            *(float2*)&C[(size_t)gr * HID + gc]       = v0;
            *(float2*)&C[(size_t)(gr + 8) * HID + gc] = v1;
        }
    }
}

// ==================== weight transpose + tf32 round ====================
__global__ void transpose_cvt(const float* __restrict__ W, float* __restrict__ Wt) {
    __shared__ float tile[32][33];
    int n0 = blockIdx.x * 32, k0 = blockIdx.y * 32;
    int tx = threadIdx.x, ty = threadIdx.y;
    #pragma unroll
    for (int j = 0; j < 4; j++)
        tile[ty + j * 8][tx] = W[(size_t)(k0 + ty + j * 8) * HID + (n0 + tx)];
    __syncthreads();
    #pragma unroll
    for (int j = 0; j < 4; j++) {
        uint32_t u = f2tf32(tile[tx][ty + j * 8]);
        Wt[(size_t)(n0 + ty + j * 8) * HID + (k0 + tx)] = __uint_as_float(u);
    }
}

// ==================== graph / elementwise kernels ====================
__global__ void deg_kernel(const int* __restrict__ dst, float* __restrict__ deg) {
    int i = blockIdx.x * blockDim.x + threadIdx.x;
    if (i < Ee) atomicAdd(&deg[dst[i]], 1.0f);
}

__global__ void scatter_add(const float* __restrict__ x, const int* __restrict__ src,
                            const int* __restrict__ dst, float* __restrict__ out, int F) {
    int e = blockIdx.x;
    int f = blockIdx.y * blockDim.x + threadIdx.x;
    if (f >= F) return;
    int s = src[e], d = dst[e];
    atomicAdd(&out[(size_t)d * F + f], x[(size_t)s * F + f]);
}

// scalar row divide (layer 1, F = 63)
__global__ void row_div(float* __restrict__ nm, const float* __restrict__ deg, int F, int do_cvt) {
    int row = blockIdx.y;
    int f = blockIdx.x * blockDim.x + threadIdx.x;
    if (f >= F) return;
    float d = deg[row];
    float v = nm[(size_t)row * F + f] * (1.0f / fmaxf(d, 1.0f));
    if (do_cvt) v = __uint_as_float(f2tf32(v));
    nm[(size_t)row * F + f] = v;
}

// float4 row divide + tf32 round (HID layers).  grid: (HID/4/256, Nn)
__global__ void row_div4(float* __restrict__ nm, const float* __restrict__ deg) {
    int row = blockIdx.y;
    int f4 = blockIdx.x * blockDim.x + threadIdx.x;
    float inv = 1.0f / fmaxf(deg[row], 1.0f);
    float4* p = (float4*)(nm + (size_t)row * HID) + f4;
    float4 v = *p;
    v.x = __uint_as_float(f2tf32(v.x * inv));
    v.y = __uint_as_float(f2tf32(v.y * inv));
    v.z = __uint_as_float(f2tf32(v.z * inv));
    v.w = __uint_as_float(f2tf32(v.w * inv));
    *p = v;
}

// ---------------- fp32 SGEMM (layer 1, K = 63) ----------------
#define BM 128
#define BN 128
#define BK 16
#define TM 8
#define TN 8

__global__ __launch_bounds__(256, 2)
void sgemm_dual(const float* __restrict__ A1, const float* __restrict__ W1,
                const float* __restrict__ A2, const float* __restrict__ W2,
                const float* __restrict__ bias, float* __restrict__ C,
                int M, int Nc, int K) {
    __shared__ float As[BK][BM + 4];
    __shared__ float Bs[BK][BN];
    int tid = threadIdx.x;
    int block_row = blockIdx.y * BM;
    int block_col = blockIdx.x * BN;
    int tr = tid / (BN / TN);
    int tc = tid % (BN / TN);

    float acc[TM][TN];
    #pragma unroll
    for (int i = 0; i < TM; i++)
        #pragma unroll
        for (int j = 0; j < TN; j++) acc[i][j] = 0.0f;

    for (int s = 0; s < 2; s++) {
        const float* A = s ? A2 : A1;
        const float* W = s ? W2 : W1;
        for (int k0 = 0; k0 < K; k0 += BK) {
            #pragma unroll
            for (int i = tid; i < BM * BK; i += 256) {
                int m = i / BK, k = i % BK;
                int gr = block_row + m, gk = k0 + k;
                As[k][m] = (gr < M && gk < K) ? A[(size_t)gr * K + gk] : 0.0f;
            }
            #pragma unroll
            for (int i = tid; i < BK * BN; i += 256) {
                int k = i / BN, n = i % BN;
                int gk = k0 + k, gc = block_col + n;
                Bs[k][n] = (gk < K && gc < Nc) ? W[(size_t)gk * Nc + gc] : 0.0f;
            }
            __syncthreads();
            #pragma unroll
            for (int k = 0; k < BK; k++) {
                float ra[TM], rb[TN];
                #pragma unroll
                for (int i = 0; i < TM; i++) ra[i] = As[k][tr * TM + i];
                #pragma unroll
                for (int j = 0; j < TN; j++) rb[j] = Bs[k][tc * TN + j];
                #pragma unroll
                for (int i = 0; i < TM; i++)
                    #pragma unroll
                    for (int j = 0; j < TN; j++)
                        acc[i][j] += ra[i] * rb[j];
            }
            __syncthreads();
        }
    }
    #pragma unroll
    for (int i = 0; i < TM; i++) {
        int gr = block_row + tr * TM + i;
        if (gr >= M) continue;
        #pragma unroll
        for (int j = 0; j < TN; j++) {
            int gc = block_col + tc * TN + j;
            if (gc >= Nc) continue;
            C[(size_t)gr * Nc + gc] = acc[i][j] + (bias ? bias[gc] : 0.0f);
        }
    }
}

// ---------------- BN stats ----------------
__global__ void bn_stats(const float* __restrict__ X,
                         const float* __restrict__ gamma, const float* __restrict__ beta,
                         float* __restrict__ scale, float* __restrict__ shift,
                         int M, int C) {
    int lane = threadIdx.x & 31;
    int rg   = threadIdx.x >> 5;
    int col  = blockIdx.x * 32 + lane;
    float s = 0.0f, s2 = 0.0f;
    if (col < C) {
        for (int r = rg; r < M; r += 8) {
            float v = X[(size_t)r * C + col];
            s += v; s2 += v * v;
        }
    }
    __shared__ float sh[8][32], sh2[8][32];
    sh[rg][lane] = s; sh2[rg][lane] = s2;
    __syncthreads();
    if (rg == 0 && col < C) {
        #pragma unroll
        for (int i = 1; i < 8; i++) { s += sh[i][lane]; s2 += sh2[i][lane]; }
        float mu  = s / (float)M;
        float var = s2 / (float)M - mu * mu;
        float sc  = gamma[col] * rsqrtf(var + EPS);
        scale[col] = sc;
        shift[col] = beta[col] - mu * sc;
    }
}

// float4 BN apply + leaky relu, optional tf32 round.  grid: (HID/4/256, Nn)
__global__ void bn_apply4(const float* __restrict__ X, float* __restrict__ Y,
                          const float* __restrict__ scale, const float* __restrict__ shift,
                          int do_cvt) {
    int row = blockIdx.y;
    int f4 = blockIdx.x * blockDim.x + threadIdx.x;
    int c = f4 * 4;
    float4 v = *((const float4*)(X + (size_t)row * HID) + f4);
    float4 sc = *((const float4*)scale + f4);
    float4 sh = *((const float4*)shift + f4);
    v.x = v.x * sc.x + sh.x; v.x = (v.x > 0.0f) ? v.x : SLOPE * v.x;
    v.y = v.y * sc.y + sh.y; v.y = (v.y > 0.0f) ? v.y : SLOPE * v.y;
    v.z = v.z * sc.z + sh.z; v.z = (v.z > 0.0f) ? v.z : SLOPE * v.z;
    v.w = v.w * sc.w + sh.w; v.w = (v.w > 0.0f) ? v.w : SLOPE * v.w;
    if (do_cvt) {
        v.x = __uint_as_float(f2tf32(v.x));
        v.y = __uint_as_float(f2tf32(v.y));
        v.z = __uint_as_float(f2tf32(v.z));
        v.w = __uint_as_float(f2tf32(v.w));
    }
    *((float4*)(Y + (size_t)row * HID) + f4) = v;
    (void)c;
}

// ---------------- pooling (round-3 proven atomic version) ----------------
__global__ void cnt_kernel(const int* __restrict__ gid, float* __restrict__ cnt) {
    int i = blockIdx.x * blockDim.x + threadIdx.x;
    if (i < Nn) atomicAdd(&cnt[gid[i]], 1.0f);
}

__global__ void pool_kernel(const float* __restrict__ x, const int* __restrict__ gid,
                            float* __restrict__ hg, int C) {
    int row = blockIdx.y;
    int c = blockIdx.x * blockDim.x + threadIdx.x;
    if (c >= C) return;
    atomicAdd(&hg[(size_t)gid[row] * C + c], x[(size_t)row * C + c]);
}

__global__ void hg_div(float* __restrict__ hg, const float* __restrict__ cnt, int C) {
    int g = blockIdx.y;
    int c = blockIdx.x * blockDim.x + threadIdx.x;
    if (c >= C) return;
    hg[(size_t)g * C + c] *= 1.0f / fmaxf(cnt[g], 1.0f);
}

// ---------------- small MLP head GEMM (round-3 proven version) ----------------
__global__ void head_gemm(const float* __restrict__ X, const float* __restrict__ W,
                          const float* __restrict__ b, float* __restrict__ Y,
                          int K, int Nc, int do_lrelu) {
    extern __shared__ float xs[];
    int r = blockIdx.y;
    for (int i = threadIdx.x; i < K; i += blockDim.x) xs[i] = X[(size_t)r * K + i];
    __syncthreads();
    int c = blockIdx.x * blockDim.x + threadIdx.x;
    if (c >= Nc) return;
    float acc = 0.0f;
    int k = 0;
    for (; k + 4 <= K; k += 4) {
        acc += xs[k    ] * W[(size_t)(k    ) * Nc + c];
        acc += xs[k + 1] * W[(size_t)(k + 1) * Nc + c];
        acc += xs[k + 2] * W[(size_t)(k + 2) * Nc + c];
        acc += xs[k + 3] * W[(size_t)(k + 3) * Nc + c];
    }
    for (; k < K; k++) acc += xs[k] * W[(size_t)k * Nc + c];
    acc += b[c];
    if (do_lrelu) acc = (acc > 0.0f) ? acc : SLOPE * acc;
    Y[(size_t)r * Nc + c] = acc;
}

// ==================== launch ====================
extern "C" void kernel_launch(void* const* d_in, const int* in_sizes, int n_in,
                              void* d_out, int out_size) {
    (void)in_sizes; (void)n_in; (void)out_size;
    const float* h     = (const float*)d_in[0];
    const int*   src   = (const int*)  d_in[1];
    const int*   dst   = (const int*)  d_in[2];
    const int*   gid   = (const int*)  d_in[3];
    const float* Ws1   = (const float*)d_in[4];
    const float* Wn1   = (const float*)d_in[5];
    const float* b1    = (const float*)d_in[6];
    const float* Ws2   = (const float*)d_in[7];
    const float* Wn2   = (const float*)d_in[8];
    const float* b2    = (const float*)d_in[9];
    const float* Ws3   = (const float*)d_in[10];
    const float* Wn3   = (const float*)d_in[11];
    const float* b3    = (const float*)d_in[12];
    const float* g1    = (const float*)d_in[13];
    const float* be1   = (const float*)d_in[14];
    const float* g2    = (const float*)d_in[15];
    const float* be2   = (const float*)d_in[16];
    const float* g3    = (const float*)d_in[17];
    const float* be3   = (const float*)d_in[18];
    const float* fc1_w = (const float*)d_in[19];
    const float* fc1_b = (const float*)d_in[20];
    const float* fc2_w = (const float*)d_in[21];
    const float* fc2_b = (const float*)d_in[22];
    const float* fc3_w = (const float*)d_in[23];
    const float* fc3_b = (const float*)d_in[24];
    float* out = (float*)d_out;

    float *nm, *x, *y, *deg, *scale, *shift, *hg, *cnt, *t1, *t2;
    float *wt2s, *wt2n, *wt3s, *wt3n;
    cudaGetSymbolAddress((void**)&nm,    g_nm);
    cudaGetSymbolAddress((void**)&x,     g_x);
    cudaGetSymbolAddress((void**)&y,     g_y);
    cudaGetSymbolAddress((void**)&deg,   g_deg);
    cudaGetSymbolAddress((void**)&scale, g_scale);
    cudaGetSymbolAddress((void**)&shift, g_shift);
    cudaGetSymbolAddress((void**)&hg,    g_hg);
    cudaGetSymbolAddress((void**)&cnt,   g_cnt);
    cudaGetSymbolAddress((void**)&t1,    g_t1);
    cudaGetSymbolAddress((void**)&t2,    g_t2);
    cudaGetSymbolAddress((void**)&wt2s,  g_wt2s);
    cudaGetSymbolAddress((void**)&wt2n,  g_wt2n);
    cudaGetSymbolAddress((void**)&wt3s,  g_wt3s);
    cudaGetSymbolAddress((void**)&wt3n,  g_wt3n);

    cudaFuncSetAttribute(tc_gemm_dual, cudaFuncAttributeMaxDynamicSharedMemorySize, TCG_SMEM_BYTES);

    cudaStream_t s = 0;

    // weight transposes (+ tf32 rounding)
    dim3 tgrid(HID / 32, HID / 32), tblk(32, 8);
    transpose_cvt<<<tgrid, tblk, 0, s>>>(Ws2, wt2s);
    transpose_cvt<<<tgrid, tblk, 0, s>>>(Wn2, wt2n);
    transpose_cvt<<<tgrid, tblk, 0, s>>>(Ws3, wt3s);
    transpose_cvt<<<tgrid, tblk, 0, s>>>(Wn3, wt3n);

    // degrees
    cudaMemsetAsync(deg, 0, Nn * sizeof(float), s);
    deg_kernel<<<Ee / 256, 256, 0, s>>>(dst, deg);

    dim3 tc_grid(HID / 128, Nn / 128);
    dim3 ew4_grid(HID / 4 / 256, Nn);

    // ---- Layer 1 (K = 63, fp32 SGEMM) ----
    cudaMemsetAsync(nm, 0, (size_t)Nn * INF * sizeof(float), s);
    scatter_add<<<dim3(Ee, 1), 64, 0, s>>>(h, src, dst, nm, INF);
    row_div<<<dim3(1, Nn), 64, 0, s>>>(nm, deg, INF, 0);
    sgemm_dual<<<dim3(HID / BN, Nn / BM), 256, 0, s>>>(h, Ws1, nm, Wn1, b1, y, Nn, HID, INF);
    bn_stats<<<HID / 32, 256, 0, s>>>(y, g1, be1, scale, shift, Nn, HID);
    bn_apply4<<<ew4_grid, 256, 0, s>>>(y, x, scale, shift, 1);

    // ---- Layer 2 (tf32 mma.sync) ----
    cudaMemsetAsync(nm, 0, (size_t)Nn * HID * sizeof(float), s);
    scatter_add<<<dim3(Ee, HID / 256), 256, 0, s>>>(x, src, dst, nm, HID);
    row_div4<<<ew4_grid, 256, 0, s>>>(nm, deg);
    tc_gemm_dual<<<tc_grid, 256, TCG_SMEM_BYTES, s>>>(x, wt2s, nm, wt2n, b2, y);
    bn_stats<<<HID / 32, 256, 0, s>>>(y, g2, be2, scale, shift, Nn, HID);
    bn_apply4<<<ew4_grid, 256, 0, s>>>(y, x, scale, shift, 1);

    // ---- Layer 3 (tf32 mma.sync) ----
    cudaMemsetAsync(nm, 0, (size_t)Nn * HID * sizeof(float), s);
    scatter_add<<<dim3(Ee, HID / 256), 256, 0, s>>>(x, src, dst, nm, HID);
    row_div4<<<ew4_grid, 256, 0, s>>>(nm, deg);
    tc_gemm_dual<<<tc_grid, 256, TCG_SMEM_BYTES, s>>>(x, wt3s, nm, wt3n, b3, y);
    bn_stats<<<HID / 32, 256, 0, s>>>(y, g3, be3, scale, shift, Nn, HID);
    bn_apply4<<<ew4_grid, 256, 0, s>>>(y, x, scale, shift, 0);

    // ---- Average pooling over graphs (round-3 atomic version) ----
    cudaMemsetAsync(hg, 0, Gg * HID * sizeof(float), s);
    cudaMemsetAsync(cnt, 0, Gg * sizeof(float), s);
    cnt_kernel<<<Nn / 256, 256, 0, s>>>(gid, cnt);
    pool_kernel<<<dim3(HID / 256, Nn), 256, 0, s>>>(x, gid, hg, HID);
    hg_div<<<dim3(HID / 256, Gg), 256, 0, s>>>(hg, cnt, HID);

    // ---- MLP head (round-3 per-graph version) ----
    head_gemm<<<dim3((HID + 127) / 128, Gg), 128, HID * sizeof(float), s>>>(
        hg, fc1_w, fc1_b, t1, HID, HID, 1);
    head_gemm<<<dim3((MIDD + 127) / 128, Gg), 128, HID * sizeof(float), s>>>(
        t1, fc2_w, fc2_b, t2, HID, MIDD, 1);
    head_gemm<<<dim3(1, Gg), 128, MIDD * sizeof(float), s>>>(
        t2, fc3_w, fc3_b, out, MIDD, NCLS, 0);
}

// round 7
// speedup vs baseline: 2.1156x; 1.4222x over previous
#include <cuda_runtime.h>
#include <cuda_fp16.h>
#include <cstdint>
#include <math.h>

// Problem constants
#define Nn   16384
#define Ee   65536
#define Gg   64
#define INF  63
#define HID  2048
#define MIDD 1024
#define NCLS 18
#define SLOPE 0.01f
#define EPS   1e-5f

// ---------------- scratch (device globals; no allocation allowed) ----------------
__device__ float  g_nm[(size_t)Nn * HID];    // neighbor sum/mean (fp32, atomic target)
__device__ __half g_nmh[(size_t)Nn * HID];   // neighbor mean (half, GEMM operand)
__device__ float  g_x [(size_t)Nn * HID];    // activations (fp32: scatter/pool)
__device__ __half g_xh[(size_t)Nn * HID];    // activations (half, GEMM operand)
__device__ float  g_y [(size_t)Nn * HID];    // GEMM output
__device__ float  g_deg[Nn];
__device__ float  g_scale[HID];
__device__ float  g_shift[HID];
__device__ float  g_hg[Gg * HID];
__device__ float  g_cnt[Gg];
__device__ float  g_t1[Gg * HID];
__device__ float  g_t2[Gg * MIDD];
// transposed fp16 weights [N rows, K cols] (K-major)
__device__ __half g_wh2s[(size_t)HID * HID];
__device__ __half g_wh2n[(size_t)HID * HID];
__device__ __half g_wh3s[(size_t)HID * HID];
__device__ __half g_wh3n[(size_t)HID * HID];

// ==================== helpers ====================
__device__ __forceinline__ uint32_t smem_u32(const void* p) {
    uint32_t a;
    asm("{ .reg .u64 t; cvta.to.shared.u64 t, %1; cvt.u32.u64 %0, t; }" : "=r"(a) : "l"(p));
    return a;
}
__device__ __forceinline__ void cp_async16(uint32_t dst, const void* src) {
    asm volatile("cp.async.cg.shared.global [%0], [%1], 16;" :: "r"(dst), "l"(src) : "memory");
}
__device__ __forceinline__ void cp_commit() {
    asm volatile("cp.async.commit_group;" ::: "memory");
}
__device__ __forceinline__ void mma_f16(float* d, const uint32_t* a, const uint32_t* b) {
    asm volatile(
        "mma.sync.aligned.m16n8k16.row.col.f32.f16.f16.f32 "
        "{%0,%1,%2,%3}, {%4,%5,%6,%7}, {%8,%9}, {%0,%1,%2,%3};"
        : "+f"(d[0]), "+f"(d[1]), "+f"(d[2]), "+f"(d[3])
        : "r"(a[0]), "r"(a[1]), "r"(a[2]), "r"(a[3]), "r"(b[0]), "r"(b[1]));
}

// ==================== fp16 mma.sync dual-source GEMM (3-stage pipeline) ====================
// C[M=16384, N=2048] = A1@B1^T + A2@B2^T + bias.  K = 2048 per source, fp16 in, fp32 accum.
// K-chunk 64 (4 phases of k16).  Row pitch 144 B (72 halves) -> conflict-free frag loads.
#define PADW 36                                  // b32 words per smem row
#define ROWB 144                                 // bytes per smem row
#define OPB  (128 * ROWB)                        // one operand tile = 18432 B
#define STAGE_BYTES (2 * OPB)                    // A + B = 36864 B
#define NSTAGE 3
#define TCG_SMEM_BYTES (NSTAGE * STAGE_BYTES)    // 110592 B
#define KCH 64                                   // K per chunk

__device__ __forceinline__ void tcg_issue_chunk(uint32_t sb, int stage, int tid,
                                                const __half* A, const __half* B,
                                                int rowBlk, int colBlk, int k0) {
    uint32_t base = sb + (uint32_t)stage * STAGE_BYTES;
    #pragma unroll
    for (int i = 0; i < 4; i++) {
        int t = tid + i * 256;
        int r = t >> 3, sg = t & 7;
        uint32_t off = (uint32_t)r * ROWB + (uint32_t)sg * 16;
        cp_async16(base + off, A + (size_t)(rowBlk + r) * HID + k0 + sg * 8);
        cp_async16(base + OPB + off, B + (size_t)(colBlk + r) * HID + k0 + sg * 8);
    }
}

__global__ void __launch_bounds__(256, 2)
tc_gemm_dual(const __half* __restrict__ A1, const __half* __restrict__ B1,
             const __half* __restrict__ A2, const __half* __restrict__ B2,
             const float* __restrict__ bias, float* __restrict__ C) {
    extern __shared__ __align__(16) float smem[];
    uint32_t sb = smem_u32(smem);
    const int tid  = threadIdx.x;
    const int wid  = tid >> 5;
    const int lane = tid & 31;
    const int rowBlk = blockIdx.y * 128;
    const int colBlk = blockIdx.x * 128;
    const int wm = (wid & 1) * 64;
    const int wn = (wid >> 1) * 32;
    const int lr = lane >> 2;   // 0..7
    const int lc = lane & 3;    // 0..3

    float acc[4][4][4];
    #pragma unroll
    for (int i = 0; i < 4; i++)
        #pragma unroll
        for (int j = 0; j < 4; j++)
            #pragma unroll
            for (int k = 0; k < 4; k++) acc[i][j][k] = 0.0f;

    const int NC  = HID / KCH;  // 32 chunks per source
    const int TOT = 2 * NC;     // 64

    tcg_issue_chunk(sb, 0, tid, A1, B1, rowBlk, colBlk, 0);
    cp_commit();
    tcg_issue_chunk(sb, 1, tid, A1, B1, rowBlk, colBlk, KCH);
    cp_commit();

    int sc = 0;
    for (int c = 0; c < TOT; c++) {
        int n2 = c + 2;
        if (n2 < TOT) {
            const __half* A = (n2 < NC) ? A1 : A2;
            const __half* B = (n2 < NC) ? B1 : B2;
            int k0 = (n2 & (NC - 1)) * KCH;
            int ps = sc + 2; if (ps >= NSTAGE) ps -= NSTAGE;
            tcg_issue_chunk(sb, ps, tid, A, B, rowBlk, colBlk, k0);
        }
        cp_commit();
        asm volatile("cp.async.wait_group 2;" ::: "memory");
        __syncthreads();

        const uint32_t* As = (const uint32_t*)smem + (size_t)sc * (STAGE_BYTES / 4);
        const uint32_t* Bs = As + OPB / 4;

        #pragma unroll
        for (int kp = 0; kp < KCH; kp += 16) {
            int kw = kp >> 1;   // word offset within row
            uint32_t af[4][4], bf[4][2];
            #pragma unroll
            for (int mt = 0; mt < 4; mt++) {
                int r0 = wm + mt * 16 + lr;
                af[mt][0] = As[r0 * PADW + kw + lc];
                af[mt][1] = As[(r0 + 8) * PADW + kw + lc];
                af[mt][2] = As[r0 * PADW + kw + lc + 4];
                af[mt][3] = As[(r0 + 8) * PADW + kw + lc + 4];
            }
            #pragma unroll
            for (int nt = 0; nt < 4; nt++) {
                int n0 = wn + nt * 8 + lr;
                bf[nt][0] = Bs[n0 * PADW + kw + lc];
                bf[nt][1] = Bs[n0 * PADW + kw + lc + 4];
            }
            #pragma unroll
            for (int mt = 0; mt < 4; mt++)
                #pragma unroll
                for (int nt = 0; nt < 4; nt++)
                    mma_f16(acc[mt][nt], af[mt], bf[nt]);
        }
        __syncthreads();
        sc++; if (sc >= NSTAGE) sc = 0;
    }

    #pragma unroll
    for (int mt = 0; mt < 4; mt++) {
        #pragma unroll
        for (int nt = 0; nt < 4; nt++) {
            int gr = rowBlk + wm + mt * 16 + lr;
            int gc = colBlk + wn + nt * 8 + 2 * lc;
            float bv0 = bias[gc], bv1 = bias[gc + 1];
            float2 v0 = make_float2(acc[mt][nt][0] + bv0, acc[mt][nt][1] + bv1);
            float2 v1 = make_float2(acc[mt][nt][2] + bv0, acc[mt][nt][3] + bv1);
            *(float2*)&C[(size_t)gr * HID + gc]       = v0;
            *(float2*)&C[(size_t)(gr + 8) * HID + gc] = v1;
        }
    }
}

// ==================== weight transpose + fp16 convert ====================
// W [K,N] fp32 row-major -> Wt [N,K] half row-major.
__global__ void transpose_cvt(const float* __restrict__ W, __half* __restrict__ Wt) {
    __shared__ float tile[32][33];
    int n0 = blockIdx.x * 32, k0 = blockIdx.y * 32;
    int tx = threadIdx.x, ty = threadIdx.y;
    #pragma unroll
    for (int j = 0; j < 4; j++)
        tile[ty + j * 8][tx] = W[(size_t)(k0 + ty + j * 8) * HID + (n0 + tx)];
    __syncthreads();
    #pragma unroll
    for (int j = 0; j < 4; j++)
        Wt[(size_t)(n0 + ty + j * 8) * HID + (k0 + tx)] = __float2half_rn(tile[tx][ty + j * 8]);
}

// ==================== graph / elementwise kernels ====================
__global__ void deg_kernel(const int* __restrict__ dst, float* __restrict__ deg) {
    int i = blockIdx.x * blockDim.x + threadIdx.x;
    if (i < Ee) atomicAdd(&deg[dst[i]], 1.0f);
}

__global__ void scatter_add(const float* __restrict__ x, const int* __restrict__ src,
                            const int* __restrict__ dst, float* __restrict__ out, int F) {
    int e = blockIdx.x;
    int f = blockIdx.y * blockDim.x + threadIdx.x;
    if (f >= F) return;
    int s = src[e], d = dst[e];
    atomicAdd(&out[(size_t)d * F + f], x[(size_t)s * F + f]);
}

// scalar row divide (layer 1, F = 63)
__global__ void row_div(float* __restrict__ nm, const float* __restrict__ deg, int F) {
    int row = blockIdx.y;
    int f = blockIdx.x * blockDim.x + threadIdx.x;
    if (f >= F) return;
    float d = deg[row];
    nm[(size_t)row * F + f] *= 1.0f / fmaxf(d, 1.0f);
}

// float4 row divide -> half output (HID layers).  grid: (HID/4/256, Nn)
__global__ void row_div4h(const float* __restrict__ nm, const float* __restrict__ deg,
                          __half* __restrict__ nmh) {
    int row = blockIdx.y;
    int f4 = blockIdx.x * blockDim.x + threadIdx.x;
    float inv = 1.0f / fmaxf(deg[row], 1.0f);
    float4 v = *((const float4*)(nm + (size_t)row * HID) + f4);
    __half2 h0 = __floats2half2_rn(v.x * inv, v.y * inv);
    __half2 h1 = __floats2half2_rn(v.z * inv, v.w * inv);
    *((__half2*)(nmh + (size_t)row * HID) + f4 * 2)     = h0;
    *((__half2*)(nmh + (size_t)row * HID) + f4 * 2 + 1) = h1;
}

// ---------------- fp32 SGEMM (layer 1, K = 63) ----------------
#define BM 128
#define BN 128
#define BK 16
#define TM 8
#define TN 8

__global__ __launch_bounds__(256, 2)
void sgemm_dual(const float* __restrict__ A1, const float* __restrict__ W1,
                const float* __restrict__ A2, const float* __restrict__ W2,
                const float* __restrict__ bias, float* __restrict__ C,
                int M, int Nc, int K) {
    __shared__ float As[BK][BM + 4];
    __shared__ float Bs[BK][BN];
    int tid = threadIdx.x;
    int block_row = blockIdx.y * BM;
    int block_col = blockIdx.x * BN;
    int tr = tid / (BN / TN);
    int tc = tid % (BN / TN);

    float acc[TM][TN];
    #pragma unroll
    for (int i = 0; i < TM; i++)
        #pragma unroll
        for (int j = 0; j < TN; j++) acc[i][j] = 0.0f;

    for (int s = 0; s < 2; s++) {
        const float* A = s ? A2 : A1;
        const float* W = s ? W2 : W1;
        for (int k0 = 0; k0 < K; k0 += BK) {
            #pragma unroll
            for (int i = tid; i < BM * BK; i += 256) {
                int m = i / BK, k = i % BK;
                int gr = block_row + m, gk = k0 + k;
                As[k][m] = (gr < M && gk < K) ? A[(size_t)gr * K + gk] : 0.0f;
            }
            #pragma unroll
            for (int i = tid; i < BK * BN; i += 256) {
                int k = i / BN, n = i % BN;
                int gk = k0 + k, gc = block_col + n;
                Bs[k][n] = (gk < K && gc < Nc) ? W[(size_t)gk * Nc + gc] : 0.0f;
            }
            __syncthreads();
            #pragma unroll
            for (int k = 0; k < BK; k++) {
                float ra[TM], rb[TN];
                #pragma unroll
                for (int i = 0; i < TM; i++) ra[i] = As[k][tr * TM + i];
                #pragma unroll
                for (int j = 0; j < TN; j++) rb[j] = Bs[k][tc * TN + j];
                #pragma unroll
                for (int i = 0; i < TM; i++)
                    #pragma unroll
                    for (int j = 0; j < TN; j++)
                        acc[i][j] += ra[i] * rb[j];
            }
            __syncthreads();
        }
    }
    #pragma unroll
    for (int i = 0; i < TM; i++) {
        int gr = block_row + tr * TM + i;
        if (gr >= M) continue;
        #pragma unroll
        for (int j = 0; j < TN; j++) {
            int gc = block_col + tc * TN + j;
            if (gc >= Nc) continue;
            C[(size_t)gr * Nc + gc] = acc[i][j] + (bias ? bias[gc] : 0.0f);
        }
    }
}

// ---------------- BN stats ----------------
__global__ void bn_stats(const float* __restrict__ X,
                         const float* __restrict__ gamma, const float* __restrict__ beta,
                         float* __restrict__ scale, float* __restrict__ shift,
                         int M, int C) {
    int lane = threadIdx.x & 31;
    int rg   = threadIdx.x >> 5;
    int col  = blockIdx.x * 32 + lane;
    float s = 0.0f, s2 = 0.0f;
    if (col < C) {
        for (int r = rg; r < M; r += 8) {
            float v = X[(size_t)r * C + col];
            s += v; s2 += v * v;
        }
    }
    __shared__ float sh[8][32], sh2[8][32];
    sh[rg][lane] = s; sh2[rg][lane] = s2;
    __syncthreads();
    if (rg == 0 && col < C) {
        #pragma unroll
        for (int i = 1; i < 8; i++) { s += sh[i][lane]; s2 += sh2[i][lane]; }
        float mu  = s / (float)M;
        float var = s2 / (float)M - mu * mu;
        float sc  = gamma[col] * rsqrtf(var + EPS);
        scale[col] = sc;
        shift[col] = beta[col] - mu * sc;
    }
}

// float4 BN apply + leaky relu; optionally also emit half copy for GEMM.
// grid: (HID/4/256, Nn)
__global__ void bn_apply4(const float* __restrict__ X, float* __restrict__ Y,
                          __half* __restrict__ Yh,
                          const float* __restrict__ scale, const float* __restrict__ shift,
                          int emit_half) {
    int row = blockIdx.y;
    int f4 = blockIdx.x * blockDim.x + threadIdx.x;
    float4 v = *((const float4*)(X + (size_t)row * HID) + f4);
    float4 sc = *((const float4*)scale + f4);
    float4 sh = *((const float4*)shift + f4);
    v.x = v.x * sc.x + sh.x; v.x = (v.x > 0.0f) ? v.x : SLOPE * v.x;
    v.y = v.y * sc.y + sh.y; v.y = (v.y > 0.0f) ? v.y : SLOPE * v.y;
    v.z = v.z * sc.z + sh.z; v.z = (v.z > 0.0f) ? v.z : SLOPE * v.z;
    v.w = v.w * sc.w + sh.w; v.w = (v.w > 0.0f) ? v.w : SLOPE * v.w;
    *((float4*)(Y + (size_t)row * HID) + f4) = v;
    if (emit_half) {
        __half2 h0 = __floats2half2_rn(v.x, v.y);
        __half2 h1 = __floats2half2_rn(v.z, v.w);
        *((__half2*)(Yh + (size_t)row * HID) + f4 * 2)     = h0;
        *((__half2*)(Yh + (size_t)row * HID) + f4 * 2 + 1) = h1;
    }
}

// ---------------- pooling (proven atomic version) ----------------
__global__ void cnt_kernel(const int* __restrict__ gid, float* __restrict__ cnt) {
    int i = blockIdx.x * blockDim.x + threadIdx.x;
    if (i < Nn) atomicAdd(&cnt[gid[i]], 1.0f);
}

__global__ void pool_kernel(const float* __restrict__ x, const int* __restrict__ gid,
                            float* __restrict__ hg, int C) {
    int row = blockIdx.y;
    int c = blockIdx.x * blockDim.x + threadIdx.x;
    if (c >= C) return;
    atomicAdd(&hg[(size_t)gid[row] * C + c], x[(size_t)row * C + c]);
}

__global__ void hg_div(float* __restrict__ hg, const float* __restrict__ cnt, int C) {
    int g = blockIdx.y;
    int c = blockIdx.x * blockDim.x + threadIdx.x;
    if (c >= C) return;
    hg[(size_t)g * C + c] *= 1.0f / fmaxf(cnt[g], 1.0f);
}

// ---------------- small MLP head GEMM (proven per-graph version) ----------------
__global__ void head_gemm(const float* __restrict__ X, const float* __restrict__ W,
                          const float* __restrict__ b, float* __restrict__ Y,
                          int K, int Nc, int do_lrelu) {
    extern __shared__ float xs[];
    int r = blockIdx.y;
    for (int i = threadIdx.x; i < K; i += blockDim.x) xs[i] = X[(size_t)r * K + i];
    __syncthreads();
    int c = blockIdx.x * blockDim.x + threadIdx.x;
    if (c >= Nc) return;
    float acc = 0.0f;
    int k = 0;
    for (; k + 4 <= K; k += 4) {
        acc += xs[k    ] * W[(size_t)(k    ) * Nc + c];
        acc += xs[k + 1] * W[(size_t)(k + 1) * Nc + c];
        acc += xs[k + 2] * W[(size_t)(k + 2) * Nc + c];
        acc += xs[k + 3] * W[(size_t)(k + 3) * Nc + c];
    }
    for (; k < K; k++) acc += xs[k] * W[(size_t)k * Nc + c];
    acc += b[c];
    if (do_lrelu) acc = (acc > 0.0f) ? acc : SLOPE * acc;
    Y[(size_t)r * Nc + c] = acc;
}

// ==================== launch ====================
extern "C" void kernel_launch(void* const* d_in, const int* in_sizes, int n_in,
                              void* d_out, int out_size) {
    (void)in_sizes; (void)n_in; (void)out_size;
    const float* h     = (const float*)d_in[0];
    const int*   src   = (const int*)  d_in[1];
    const int*   dst   = (const int*)  d_in[2];
    const int*   gid   = (const int*)  d_in[3];
    const float* Ws1   = (const float*)d_in[4];
    const float* Wn1   = (const float*)d_in[5];
    const float* b1    = (const float*)d_in[6];
    const float* Ws2   = (const float*)d_in[7];
    const float* Wn2   = (const float*)d_in[8];
    const float* b2    = (const float*)d_in[9];
    const float* Ws3   = (const float*)d_in[10];
    const float* Wn3   = (const float*)d_in[11];
    const float* b3    = (const float*)d_in[12];
    const float* g1    = (const float*)d_in[13];
    const float* be1   = (const float*)d_in[14];
    const float* g2    = (const float*)d_in[15];
    const float* be2   = (const float*)d_in[16];
    const float* g3    = (const float*)d_in[17];
    const float* be3   = (const float*)d_in[18];
    const float* fc1_w = (const float*)d_in[19];
    const float* fc1_b = (const float*)d_in[20];
    const float* fc2_w = (const float*)d_in[21];
    const float* fc2_b = (const float*)d_in[22];
    const float* fc3_w = (const float*)d_in[23];
    const float* fc3_b = (const float*)d_in[24];
    float* out = (float*)d_out;

    float *nm, *x, *y, *deg, *scale, *shift, *hg, *cnt, *t1, *t2;
    __half *nmh, *xh, *wh2s, *wh2n, *wh3s, *wh3n;
    cudaGetSymbolAddress((void**)&nm,    g_nm);
    cudaGetSymbolAddress((void**)&nmh,   g_nmh);
    cudaGetSymbolAddress((void**)&x,     g_x);
    cudaGetSymbolAddress((void**)&xh,    g_xh);
    cudaGetSymbolAddress((void**)&y,     g_y);
    cudaGetSymbolAddress((void**)&deg,   g_deg);
    cudaGetSymbolAddress((void**)&scale, g_scale);
    cudaGetSymbolAddress((void**)&shift, g_shift);
    cudaGetSymbolAddress((void**)&hg,    g_hg);
    cudaGetSymbolAddress((void**)&cnt,   g_cnt);
    cudaGetSymbolAddress((void**)&t1,    g_t1);
    cudaGetSymbolAddress((void**)&t2,    g_t2);
    cudaGetSymbolAddress((void**)&wh2s,  g_wh2s);
    cudaGetSymbolAddress((void**)&wh2n,  g_wh2n);
    cudaGetSymbolAddress((void**)&wh3s,  g_wh3s);
    cudaGetSymbolAddress((void**)&wh3n,  g_wh3n);

    cudaFuncSetAttribute(tc_gemm_dual, cudaFuncAttributeMaxDynamicSharedMemorySize, TCG_SMEM_BYTES);

    cudaStream_t s = 0;

    // weight transposes (+ fp16 convert)
    dim3 tgrid(HID / 32, HID / 32), tblk(32, 8);
    transpose_cvt<<<tgrid, tblk, 0, s>>>(Ws2, wh2s);
    transpose_cvt<<<tgrid, tblk, 0, s>>>(Wn2, wh2n);
    transpose_cvt<<<tgrid, tblk, 0, s>>>(Ws3, wh3s);
    transpose_cvt<<<tgrid, tblk, 0, s>>>(Wn3, wh3n);

    // degrees
    cudaMemsetAsync(deg, 0, Nn * sizeof(float), s);
    deg_kernel<<<Ee / 256, 256, 0, s>>>(dst, deg);

    dim3 tc_grid(HID / 128, Nn / 128);
    dim3 ew4_grid(HID / 4 / 256, Nn);

    // ---- Layer 1 (K = 63, fp32 SGEMM) ----
    cudaMemsetAsync(nm, 0, (size_t)Nn * INF * sizeof(float), s);
    scatter_add<<<dim3(Ee, 1), 64, 0, s>>>(h, src, dst, nm, INF);
    row_div<<<dim3(1, Nn), 64, 0, s>>>(nm, deg, INF);
    sgemm_dual<<<dim3(HID / BN, Nn / BM), 256, 0, s>>>(h, Ws1, nm, Wn1, b1, y, Nn, HID, INF);
    bn_stats<<<HID / 32, 256, 0, s>>>(y, g1, be1, scale, shift, Nn, HID);
    bn_apply4<<<ew4_grid, 256, 0, s>>>(y, x, xh, scale, shift, 1);

    // ---- Layer 2 (fp16 mma.sync) ----
    cudaMemsetAsync(nm, 0, (size_t)Nn * HID * sizeof(float), s);
    scatter_add<<<dim3(Ee, HID / 256), 256, 0, s>>>(x, src, dst, nm, HID);
    row_div4h<<<ew4_grid, 256, 0, s>>>(nm, deg, nmh);
    tc_gemm_dual<<<tc_grid, 256, TCG_SMEM_BYTES, s>>>(xh, wh2s, nmh, wh2n, b2, y);
    bn_stats<<<HID / 32, 256, 0, s>>>(y, g2, be2, scale, shift, Nn, HID);
    bn_apply4<<<ew4_grid, 256, 0, s>>>(y, x, xh, scale, shift, 1);

    // ---- Layer 3 (fp16 mma.sync) ----
    cudaMemsetAsync(nm, 0, (size_t)Nn * HID * sizeof(float), s);
    scatter_add<<<dim3(Ee, HID / 256), 256, 0, s>>>(x, src, dst, nm, HID);
    row_div4h<<<ew4_grid, 256, 0, s>>>(nm, deg, nmh);
    tc_gemm_dual<<<tc_grid, 256, TCG_SMEM_BYTES, s>>>(xh, wh3s, nmh, wh3n, b3, y);
    bn_stats<<<HID / 32, 256, 0, s>>>(y, g3, be3, scale, shift, Nn, HID);
    bn_apply4<<<ew4_grid, 256, 0, s>>>(y, x, xh, scale, shift, 0);

    // ---- Average pooling over graphs ----
    cudaMemsetAsync(hg, 0, Gg * HID * sizeof(float), s);
    cudaMemsetAsync(cnt, 0, Gg * sizeof(float), s);
    cnt_kernel<<<Nn / 256, 256, 0, s>>>(gid, cnt);
    pool_kernel<<<dim3(HID / 256, Nn), 256, 0, s>>>(x, gid, hg, HID);
    hg_div<<<dim3(HID / 256, Gg), 256, 0, s>>>(hg, cnt, HID);

    // ---- MLP head ----
    head_gemm<<<dim3((HID + 127) / 128, Gg), 128, HID * sizeof(float), s>>>(
        hg, fc1_w, fc1_b, t1, HID, HID, 1);
    head_gemm<<<dim3((MIDD + 127) / 128, Gg), 128, HID * sizeof(float), s>>>(
        t1, fc2_w, fc2_b, t2, HID, MIDD, 1);
    head_gemm<<<dim3(1, Gg), 128, MIDD * sizeof(float), s>>>(
        t2, fc3_w, fc3_b, out, MIDD, NCLS, 0);
}

// round 8
// speedup vs baseline: 2.3322x; 1.1024x over previous
#include <cuda_runtime.h>
#include <cuda_fp16.h>
#include <cstdint>
#include <math.h>

// Problem constants
#define Nn   16384
#define Ee   65536
#define Gg   64
#define INF  63
#define HID  2048
#define MIDD 1024
#define NCLS 18
#define SLOPE 0.01f
#define EPS   1e-5f

// ---------------- scratch (device globals; no allocation allowed) ----------------
__device__ float  g_nm[(size_t)Nn * HID];    // neighbor sum/mean (fp32, atomic target)
__device__ __half g_nmh[(size_t)Nn * HID];   // neighbor mean (half, GEMM operand)
__device__ __half g_xh[(size_t)Nn * HID];    // activations (half, GEMM operand + scatter src)
__device__ float  g_y [(size_t)Nn * HID];    // GEMM output
__device__ float  g_deg[Nn];
__device__ float  g_scale[HID];
__device__ float  g_shift[HID];
__device__ float  g_colsum[HID];
__device__ float  g_colsq[HID];
__device__ float  g_hg[Gg * HID];
__device__ float  g_cnt[Gg];
__device__ float  g_t1[Gg * HID];
__device__ float  g_t2[Gg * MIDD];
// transposed fp16 weights [N rows, K cols] (K-major)
__device__ __half g_wh2s[(size_t)HID * HID];
__device__ __half g_wh2n[(size_t)HID * HID];
__device__ __half g_wh3s[(size_t)HID * HID];
__device__ __half g_wh3n[(size_t)HID * HID];

// ==================== helpers ====================
__device__ __forceinline__ uint32_t smem_u32(const void* p) {
    uint32_t a;
    asm("{ .reg .u64 t; cvta.to.shared.u64 t, %1; cvt.u32.u64 %0, t; }" : "=r"(a) : "l"(p));
    return a;
}
__device__ __forceinline__ void cp_async16(uint32_t dst, const void* src) {
    asm volatile("cp.async.cg.shared.global [%0], [%1], 16;" :: "r"(dst), "l"(src) : "memory");
}
__device__ __forceinline__ void cp_commit() {
    asm volatile("cp.async.commit_group;" ::: "memory");
}
__device__ __forceinline__ void mma_f16(float* d, const uint32_t* a, const uint32_t* b) {
    asm volatile(
        "mma.sync.aligned.m16n8k16.row.col.f32.f16.f16.f32 "
        "{%0,%1,%2,%3}, {%4,%5,%6,%7}, {%8,%9}, {%0,%1,%2,%3};"
        : "+f"(d[0]), "+f"(d[1]), "+f"(d[2]), "+f"(d[3])
        : "r"(a[0]), "r"(a[1]), "r"(a[2]), "r"(a[3]), "r"(b[0]), "r"(b[1]));
}

// ==================== fp16 mma.sync dual-source GEMM + fused BN column stats ====================
// C = A1@B1^T + A2@B2^T + bias; also accumulates per-column sum / sum-of-squares.
#define PADW 36
#define ROWB 144
#define OPB  (128 * ROWB)
#define STAGE_BYTES (2 * OPB)
#define NSTAGE 3
#define TCG_SMEM_BYTES (NSTAGE * STAGE_BYTES)    // 110592 B
#define KCH 64

__device__ __forceinline__ void tcg_issue_chunk(uint32_t sb, int stage, int tid,
                                                const __half* A, const __half* B,
                                                int rowBlk, int colBlk, int k0) {
    uint32_t base = sb + (uint32_t)stage * STAGE_BYTES;
    #pragma unroll
    for (int i = 0; i < 4; i++) {
        int t = tid + i * 256;
        int r = t >> 3, sg = t & 7;
        uint32_t off = (uint32_t)r * ROWB + (uint32_t)sg * 16;
        cp_async16(base + off, A + (size_t)(rowBlk + r) * HID + k0 + sg * 8);
        cp_async16(base + OPB + off, B + (size_t)(colBlk + r) * HID + k0 + sg * 8);
    }
}

__global__ void __launch_bounds__(256, 2)
tc_gemm_dual(const __half* __restrict__ A1, const __half* __restrict__ B1,
             const __half* __restrict__ A2, const __half* __restrict__ B2,
             const float* __restrict__ bias, float* __restrict__ C,
             float* __restrict__ colsum, float* __restrict__ colsq) {
    extern __shared__ __align__(16) float smem[];
    uint32_t sb = smem_u32(smem);
    const int tid  = threadIdx.x;
    const int wid  = tid >> 5;
    const int lane = tid & 31;
    const int rowBlk = blockIdx.y * 128;
    const int colBlk = blockIdx.x * 128;
    const int wm = (wid & 1) * 64;
    const int wn = (wid >> 1) * 32;
    const int lr = lane >> 2;
    const int lc = lane & 3;

    float acc[4][4][4];
    #pragma unroll
    for (int i = 0; i < 4; i++)
        #pragma unroll
        for (int j = 0; j < 4; j++)
            #pragma unroll
            for (int k = 0; k < 4; k++) acc[i][j][k] = 0.0f;

    const int NC  = HID / KCH;
    const int TOT = 2 * NC;

    tcg_issue_chunk(sb, 0, tid, A1, B1, rowBlk, colBlk, 0);
    cp_commit();
    tcg_issue_chunk(sb, 1, tid, A1, B1, rowBlk, colBlk, KCH);
    cp_commit();

    int sc = 0;
    for (int c = 0; c < TOT; c++) {
        int n2 = c + 2;
        if (n2 < TOT) {
            const __half* A = (n2 < NC) ? A1 : A2;
            const __half* B = (n2 < NC) ? B1 : B2;
            int k0 = (n2 & (NC - 1)) * KCH;
            int ps = sc + 2; if (ps >= NSTAGE) ps -= NSTAGE;
            tcg_issue_chunk(sb, ps, tid, A, B, rowBlk, colBlk, k0);
        }
        cp_commit();
        asm volatile("cp.async.wait_group 2;" ::: "memory");
        __syncthreads();

        const uint32_t* As = (const uint32_t*)smem + (size_t)sc * (STAGE_BYTES / 4);
        const uint32_t* Bs = As + OPB / 4;

        #pragma unroll
        for (int kp = 0; kp < KCH; kp += 16) {
            int kw = kp >> 1;
            uint32_t af[4][4], bf[4][2];
            #pragma unroll
            for (int mt = 0; mt < 4; mt++) {
                int r0 = wm + mt * 16 + lr;
                af[mt][0] = As[r0 * PADW + kw + lc];
                af[mt][1] = As[(r0 + 8) * PADW + kw + lc];
                af[mt][2] = As[r0 * PADW + kw + lc + 4];
                af[mt][3] = As[(r0 + 8) * PADW + kw + lc + 4];
            }
            #pragma unroll
            for (int nt = 0; nt < 4; nt++) {
                int n0 = wn + nt * 8 + lr;
                bf[nt][0] = Bs[n0 * PADW + kw + lc];
                bf[nt][1] = Bs[n0 * PADW + kw + lc + 4];
            }
            #pragma unroll
            for (int mt = 0; mt < 4; mt++)
                #pragma unroll
                for (int nt = 0; nt < 4; nt++)
                    mma_f16(acc[mt][nt], af[mt], bf[nt]);
        }
        __syncthreads();
        sc++; if (sc >= NSTAGE) sc = 0;
    }

    // epilogue: store +bias, and accumulate per-column sum / sumsq
    #pragma unroll
    for (int nt = 0; nt < 4; nt++) {
        int gc = colBlk + wn + nt * 8 + 2 * lc;
        float bv0 = bias[gc], bv1 = bias[gc + 1];
        float s0 = 0.f, s1 = 0.f, q0 = 0.f, q1 = 0.f;
        #pragma unroll
        for (int mt = 0; mt < 4; mt++) {
            int gr = rowBlk + wm + mt * 16 + lr;
            float v00 = acc[mt][nt][0] + bv0;
            float v01 = acc[mt][nt][1] + bv1;
            float v10 = acc[mt][nt][2] + bv0;
            float v11 = acc[mt][nt][3] + bv1;
            *(float2*)&C[(size_t)gr * HID + gc]       = make_float2(v00, v01);
            *(float2*)&C[(size_t)(gr + 8) * HID + gc] = make_float2(v10, v11);
            s0 += v00 + v10;  s1 += v01 + v11;
            q0 += v00 * v00 + v10 * v10;
            q1 += v01 * v01 + v11 * v11;
        }
        #pragma unroll
        for (int st = 4; st <= 16; st <<= 1) {
            s0 += __shfl_xor_sync(0xFFFFFFFF, s0, st);
            s1 += __shfl_xor_sync(0xFFFFFFFF, s1, st);
            q0 += __shfl_xor_sync(0xFFFFFFFF, q0, st);
            q1 += __shfl_xor_sync(0xFFFFFFFF, q1, st);
        }
        if (lr == 0) {
            atomicAdd(&colsum[gc],     s0);
            atomicAdd(&colsum[gc + 1], s1);
            atomicAdd(&colsq[gc],      q0);
            atomicAdd(&colsq[gc + 1],  q1);
        }
    }
}

// colsum/colsq -> scale/shift
__global__ void bn_scale(const float* __restrict__ colsum, const float* __restrict__ colsq,
                         const float* __restrict__ gamma, const float* __restrict__ beta,
                         float* __restrict__ scale, float* __restrict__ shift) {
    int c = blockIdx.x * blockDim.x + threadIdx.x;
    float mu  = colsum[c] / (float)Nn;
    float var = colsq[c] / (float)Nn - mu * mu;
    float sc  = gamma[c] * rsqrtf(var + EPS);
    scale[c] = sc;
    shift[c] = beta[c] - mu * sc;
}

// ==================== weight transpose + fp16 convert ====================
__global__ void transpose_cvt(const float* __restrict__ W, __half* __restrict__ Wt) {
    __shared__ float tile[32][33];
    int n0 = blockIdx.x * 32, k0 = blockIdx.y * 32;
    int tx = threadIdx.x, ty = threadIdx.y;
    #pragma unroll
    for (int j = 0; j < 4; j++)
        tile[ty + j * 8][tx] = W[(size_t)(k0 + ty + j * 8) * HID + (n0 + tx)];
    __syncthreads();
    #pragma unroll
    for (int j = 0; j < 4; j++)
        Wt[(size_t)(n0 + ty + j * 8) * HID + (k0 + tx)] = __float2half_rn(tile[tx][ty + j * 8]);
}

// ==================== graph / elementwise kernels ====================
__global__ void deg_kernel(const int* __restrict__ dst, float* __restrict__ deg) {
    int i = blockIdx.x * blockDim.x + threadIdx.x;
    if (i < Ee) atomicAdd(&deg[dst[i]], 1.0f);
}

// layer-1 scatter (fp32 features, F = 63)
__global__ void scatter_add(const float* __restrict__ x, const int* __restrict__ src,
                            const int* __restrict__ dst, float* __restrict__ out, int F) {
    int e = blockIdx.x;
    int f = blockIdx.y * blockDim.x + threadIdx.x;
    if (f >= F) return;
    int s = src[e], d = dst[e];
    atomicAdd(&out[(size_t)d * F + f], x[(size_t)s * F + f]);
}

// HID-layer scatter: read half2, fp32 atomic accumulate.  grid: (Ee, HID/2/128), block 128
__global__ void scatter_add_h(const __half* __restrict__ xh, const int* __restrict__ src,
                              const int* __restrict__ dst, float* __restrict__ out) {
    int e = blockIdx.x;
    int f2 = blockIdx.y * blockDim.x + threadIdx.x;
    int s = src[e], d = dst[e];
    __half2 v = *((const __half2*)(xh + (size_t)s * HID) + f2);
    float2 f = __half22float2(v);
    atomicAdd(&out[(size_t)d * HID + f2 * 2],     f.x);
    atomicAdd(&out[(size_t)d * HID + f2 * 2 + 1], f.y);
}

// scalar row divide (layer 1, F = 63)
__global__ void row_div(float* __restrict__ nm, const float* __restrict__ deg, int F) {
    int row = blockIdx.y;
    int f = blockIdx.x * blockDim.x + threadIdx.x;
    if (f >= F) return;
    float d = deg[row];
    nm[(size_t)row * F + f] *= 1.0f / fmaxf(d, 1.0f);
}

// float4 row divide -> half output.  grid: (HID/4/256, Nn)
__global__ void row_div4h(const float* __restrict__ nm, const float* __restrict__ deg,
                          __half* __restrict__ nmh) {
    int row = blockIdx.y;
    int f4 = blockIdx.x * blockDim.x + threadIdx.x;
    float inv = 1.0f / fmaxf(deg[row], 1.0f);
    float4 v = *((const float4*)(nm + (size_t)row * HID) + f4);
    __half2 h0 = __floats2half2_rn(v.x * inv, v.y * inv);
    __half2 h1 = __floats2half2_rn(v.z * inv, v.w * inv);
    *((__half2*)(nmh + (size_t)row * HID) + f4 * 2)     = h0;
    *((__half2*)(nmh + (size_t)row * HID) + f4 * 2 + 1) = h1;
}

// ---------------- fp32 SGEMM (layer 1, K = 63) ----------------
#define BM 128
#define BN 128
#define BK 16
#define TM 8
#define TN 8

__global__ __launch_bounds__(256, 2)
void sgemm_dual(const float* __restrict__ A1, const float* __restrict__ W1,
                const float* __restrict__ A2, const float* __restrict__ W2,
                const float* __restrict__ bias, float* __restrict__ C,
                int M, int Nc, int K) {
    __shared__ float As[BK][BM + 4];
    __shared__ float Bs[BK][BN];
    int tid = threadIdx.x;
    int block_row = blockIdx.y * BM;
    int block_col = blockIdx.x * BN;
    int tr = tid / (BN / TN);
    int tc = tid % (BN / TN);

    float acc[TM][TN];
    #pragma unroll
    for (int i = 0; i < TM; i++)
        #pragma unroll
        for (int j = 0; j < TN; j++) acc[i][j] = 0.0f;

    for (int s = 0; s < 2; s++) {
        const float* A = s ? A2 : A1;
        const float* W = s ? W2 : W1;
        for (int k0 = 0; k0 < K; k0 += BK) {
            #pragma unroll
            for (int i = tid; i < BM * BK; i += 256) {
                int m = i / BK, k = i % BK;
                int gr = block_row + m, gk = k0 + k;
                As[k][m] = (gr < M && gk < K) ? A[(size_t)gr * K + gk] : 0.0f;
            }
            #pragma unroll
            for (int i = tid; i < BK * BN; i += 256) {
                int k = i / BN, n = i % BN;
                int gk = k0 + k, gc = block_col + n;
                Bs[k][n] = (gk < K && gc < Nc) ? W[(size_t)gk * Nc + gc] : 0.0f;
            }
            __syncthreads();
            #pragma unroll
            for (int k = 0; k < BK; k++) {
                float ra[TM], rb[TN];
                #pragma unroll
                for (int i = 0; i < TM; i++) ra[i] = As[k][tr * TM + i];
                #pragma unroll
                for (int j = 0; j < TN; j++) rb[j] = Bs[k][tc * TN + j];
                #pragma unroll
                for (int i = 0; i < TM; i++)
                    #pragma unroll
                    for (int j = 0; j < TN; j++)
                        acc[i][j] += ra[i] * rb[j];
            }
            __syncthreads();
        }
    }
    #pragma unroll
    for (int i = 0; i < TM; i++) {
        int gr = block_row + tr * TM + i;
        if (gr >= M) continue;
        #pragma unroll
        for (int j = 0; j < TN; j++) {
            int gc = block_col + tc * TN + j;
            if (gc >= Nc) continue;
            C[(size_t)gr * Nc + gc] = acc[i][j] + (bias ? bias[gc] : 0.0f);
        }
    }
}

// ---------------- BN stats (layer 1 only) ----------------
__global__ void bn_stats(const float* __restrict__ X,
                         const float* __restrict__ gamma, const float* __restrict__ beta,
                         float* __restrict__ scale, float* __restrict__ shift,
                         int M, int C) {
    int lane = threadIdx.x & 31;
    int rg   = threadIdx.x >> 5;
    int col  = blockIdx.x * 32 + lane;
    float s = 0.0f, s2 = 0.0f;
    if (col < C) {
        for (int r = rg; r < M; r += 8) {
            float v = X[(size_t)r * C + col];
            s += v; s2 += v * v;
        }
    }
    __shared__ float sh[8][32], sh2[8][32];
    sh[rg][lane] = s; sh2[rg][lane] = s2;
    __syncthreads();
    if (rg == 0 && col < C) {
        #pragma unroll
        for (int i = 1; i < 8; i++) { s += sh[i][lane]; s2 += sh2[i][lane]; }
        float mu  = s / (float)M;
        float var = s2 / (float)M - mu * mu;
        float sc  = gamma[col] * rsqrtf(var + EPS);
        scale[col] = sc;
        shift[col] = beta[col] - mu * sc;
    }
}

// BN apply + leaky relu -> half output only.  grid: (HID/4/256, Nn)
__global__ void bn_apply_h(const float* __restrict__ X, __half* __restrict__ Yh,
                           const float* __restrict__ scale, const float* __restrict__ shift) {
    int row = blockIdx.y;
    int f4 = blockIdx.x * blockDim.x + threadIdx.x;
    float4 v = *((const float4*)(X + (size_t)row * HID) + f4);
    float4 sc = *((const float4*)scale + f4);
    float4 sh = *((const float4*)shift + f4);
    v.x = v.x * sc.x + sh.x; v.x = (v.x > 0.0f) ? v.x : SLOPE * v.x;
    v.y = v.y * sc.y + sh.y; v.y = (v.y > 0.0f) ? v.y : SLOPE * v.y;
    v.z = v.z * sc.z + sh.z; v.z = (v.z > 0.0f) ? v.z : SLOPE * v.z;
    v.w = v.w * sc.w + sh.w; v.w = (v.w > 0.0f) ? v.w : SLOPE * v.w;
    __half2 h0 = __floats2half2_rn(v.x, v.y);
    __half2 h1 = __floats2half2_rn(v.z, v.w);
    *((__half2*)(Yh + (size_t)row * HID) + f4 * 2)     = h0;
    *((__half2*)(Yh + (size_t)row * HID) + f4 * 2 + 1) = h1;
}

// layer-3: BN apply + leaky relu + pooled atomic accumulate (no x write, no pool pass)
__global__ void bn_apply_pool(const float* __restrict__ X, const int* __restrict__ gid,
                              const float* __restrict__ scale, const float* __restrict__ shift,
                              float* __restrict__ hg) {
    int row = blockIdx.y;
    int f4 = blockIdx.x * blockDim.x + threadIdx.x;
    float4 v = *((const float4*)(X + (size_t)row * HID) + f4);
    float4 sc = *((const float4*)scale + f4);
    float4 sh = *((const float4*)shift + f4);
    v.x = v.x * sc.x + sh.x; v.x = (v.x > 0.0f) ? v.x : SLOPE * v.x;
    v.y = v.y * sc.y + sh.y; v.y = (v.y > 0.0f) ? v.y : SLOPE * v.y;
    v.z = v.z * sc.z + sh.z; v.z = (v.z > 0.0f) ? v.z : SLOPE * v.z;
    v.w = v.w * sc.w + sh.w; v.w = (v.w > 0.0f) ? v.w : SLOPE * v.w;
    int g = gid[row];
    int c = f4 * 4;
    float* dst = hg + (size_t)g * HID + c;
    atomicAdd(dst,     v.x);
    atomicAdd(dst + 1, v.y);
    atomicAdd(dst + 2, v.z);
    atomicAdd(dst + 3, v.w);
}

// ---------------- pooling tail ----------------
__global__ void cnt_kernel(const int* __restrict__ gid, float* __restrict__ cnt) {
    int i = blockIdx.x * blockDim.x + threadIdx.x;
    if (i < Nn) atomicAdd(&cnt[gid[i]], 1.0f);
}

__global__ void hg_div(float* __restrict__ hg, const float* __restrict__ cnt, int C) {
    int g = blockIdx.y;
    int c = blockIdx.x * blockDim.x + threadIdx.x;
    if (c >= C) return;
    hg[(size_t)g * C + c] *= 1.0f / fmaxf(cnt[g], 1.0f);
}

// ---------------- small MLP head GEMM ----------------
__global__ void head_gemm(const float* __restrict__ X, const float* __restrict__ W,
                          const float* __restrict__ b, float* __restrict__ Y,
                          int K, int Nc, int do_lrelu) {
    extern __shared__ float xs[];
    int r = blockIdx.y;
    for (int i = threadIdx.x; i < K; i += blockDim.x) xs[i] = X[(size_t)r * K + i];
    __syncthreads();
    int c = blockIdx.x * blockDim.x + threadIdx.x;
    if (c >= Nc) return;
    float acc = 0.0f;
    int k = 0;
    for (; k + 4 <= K; k += 4) {
        acc += xs[k    ] * W[(size_t)(k    ) * Nc + c];
        acc += xs[k + 1] * W[(size_t)(k + 1) * Nc + c];
        acc += xs[k + 2] * W[(size_t)(k + 2) * Nc + c];
        acc += xs[k + 3] * W[(size_t)(k + 3) * Nc + c];
    }
    for (; k < K; k++) acc += xs[k] * W[(size_t)k * Nc + c];
    acc += b[c];
    if (do_lrelu) acc = (acc > 0.0f) ? acc : SLOPE * acc;
    Y[(size_t)r * Nc + c] = acc;
}

// ==================== launch ====================
extern "C" void kernel_launch(void* const* d_in, const int* in_sizes, int n_in,
                              void* d_out, int out_size) {
    (void)in_sizes; (void)n_in; (void)out_size;
    const float* h     = (const float*)d_in[0];
    const int*   src   = (const int*)  d_in[1];
    const int*   dst   = (const int*)  d_in[2];
    const int*   gid   = (const int*)  d_in[3];
    const float* Ws1   = (const float*)d_in[4];
    const float* Wn1   = (const float*)d_in[5];
    const float* b1    = (const float*)d_in[6];
    const float* Ws2   = (const float*)d_in[7];
    const float* Wn2   = (const float*)d_in[8];
    const float* b2    = (const float*)d_in[9];
    const float* Ws3   = (const float*)d_in[10];
    const float* Wn3   = (const float*)d_in[11];
    const float* b3    = (const float*)d_in[12];
    const float* g1    = (const float*)d_in[13];
    const float* be1   = (const float*)d_in[14];
    const float* g2    = (const float*)d_in[15];
    const float* be2   = (const float*)d_in[16];
    const float* g3    = (const float*)d_in[17];
    const float* be3   = (const float*)d_in[18];
    const float* fc1_w = (const float*)d_in[19];
    const float* fc1_b = (const float*)d_in[20];
    const float* fc2_w = (const float*)d_in[21];
    const float* fc2_b = (const float*)d_in[22];
    const float* fc3_w = (const float*)d_in[23];
    const float* fc3_b = (const float*)d_in[24];
    float* out = (float*)d_out;

    float *nm, *y, *deg, *scale, *shift, *colsum, *colsq, *hg, *cnt, *t1, *t2;
    __half *nmh, *xh, *wh2s, *wh2n, *wh3s, *wh3n;
    cudaGetSymbolAddress((void**)&nm,     g_nm);
    cudaGetSymbolAddress((void**)&nmh,    g_nmh);
    cudaGetSymbolAddress((void**)&xh,     g_xh);
    cudaGetSymbolAddress((void**)&y,      g_y);
    cudaGetSymbolAddress((void**)&deg,    g_deg);
    cudaGetSymbolAddress((void**)&scale,  g_scale);
    cudaGetSymbolAddress((void**)&shift,  g_shift);
    cudaGetSymbolAddress((void**)&colsum, g_colsum);
    cudaGetSymbolAddress((void**)&colsq,  g_colsq);
    cudaGetSymbolAddress((void**)&hg,     g_hg);
    cudaGetSymbolAddress((void**)&cnt,    g_cnt);
    cudaGetSymbolAddress((void**)&t1,     g_t1);
    cudaGetSymbolAddress((void**)&t2,     g_t2);
    cudaGetSymbolAddress((void**)&wh2s,   g_wh2s);
    cudaGetSymbolAddress((void**)&wh2n,   g_wh2n);
    cudaGetSymbolAddress((void**)&wh3s,   g_wh3s);
    cudaGetSymbolAddress((void**)&wh3n,   g_wh3n);

    cudaFuncSetAttribute(tc_gemm_dual, cudaFuncAttributeMaxDynamicSharedMemorySize, TCG_SMEM_BYTES);

    cudaStream_t s = 0;

    // weight transposes (+ fp16 convert)
    dim3 tgrid(HID / 32, HID / 32), tblk(32, 8);
    transpose_cvt<<<tgrid, tblk, 0, s>>>(Ws2, wh2s);
    transpose_cvt<<<tgrid, tblk, 0, s>>>(Wn2, wh2n);
    transpose_cvt<<<tgrid, tblk, 0, s>>>(Ws3, wh3s);
    transpose_cvt<<<tgrid, tblk, 0, s>>>(Wn3, wh3n);

    // degrees
    cudaMemsetAsync(deg, 0, Nn * sizeof(float), s);
    deg_kernel<<<Ee / 256, 256, 0, s>>>(dst, deg);

    dim3 tc_grid(HID / 128, Nn / 128);
    dim3 ew4_grid(HID / 4 / 256, Nn);

    // ---- Layer 1 (K = 63, fp32 SGEMM) ----
    cudaMemsetAsync(nm, 0, (size_t)Nn * INF * sizeof(float), s);
    scatter_add<<<dim3(Ee, 1), 64, 0, s>>>(h, src, dst, nm, INF);
    row_div<<<dim3(1, Nn), 64, 0, s>>>(nm, deg, INF);
    sgemm_dual<<<dim3(HID / BN, Nn / BM), 256, 0, s>>>(h, Ws1, nm, Wn1, b1, y, Nn, HID, INF);
    bn_stats<<<HID / 32, 256, 0, s>>>(y, g1, be1, scale, shift, Nn, HID);
    bn_apply_h<<<ew4_grid, 256, 0, s>>>(y, xh, scale, shift);

    // ---- Layer 2 (fp16 mma.sync, fused BN stats) ----
    cudaMemsetAsync(nm, 0, (size_t)Nn * HID * sizeof(float), s);
    scatter_add_h<<<dim3(Ee, HID / 2 / 128), 128, 0, s>>>(xh, src, dst, nm);
    row_div4h<<<ew4_grid, 256, 0, s>>>(nm, deg, nmh);
    cudaMemsetAsync(colsum, 0, HID * sizeof(float), s);
    cudaMemsetAsync(colsq,  0, HID * sizeof(float), s);
    tc_gemm_dual<<<tc_grid, 256, TCG_SMEM_BYTES, s>>>(xh, wh2s, nmh, wh2n, b2, y, colsum, colsq);
    bn_scale<<<HID / 256, 256, 0, s>>>(colsum, colsq, g2, be2, scale, shift);
    bn_apply_h<<<ew4_grid, 256, 0, s>>>(y, xh, scale, shift);

    // ---- Layer 3 (fp16 mma.sync, fused BN stats + fused pooling) ----
    cudaMemsetAsync(nm, 0, (size_t)Nn * HID * sizeof(float), s);
    scatter_add_h<<<dim3(Ee, HID / 2 / 128), 128, 0, s>>>(xh, src, dst, nm);
    row_div4h<<<ew4_grid, 256, 0, s>>>(nm, deg, nmh);
    cudaMemsetAsync(colsum, 0, HID * sizeof(float), s);
    cudaMemsetAsync(colsq,  0, HID * sizeof(float), s);
    tc_gemm_dual<<<tc_grid, 256, TCG_SMEM_BYTES, s>>>(xh, wh3s, nmh, wh3n, b3, y, colsum, colsq);
    bn_scale<<<HID / 256, 256, 0, s>>>(colsum, colsq, g3, be3, scale, shift);

    cudaMemsetAsync(hg, 0, Gg * HID * sizeof(float), s);
    cudaMemsetAsync(cnt, 0, Gg * sizeof(float), s);
    cnt_kernel<<<Nn / 256, 256, 0, s>>>(gid, cnt);
    bn_apply_pool<<<ew4_grid, 256, 0, s>>>(y, gid, scale, shift, hg);
    hg_div<<<dim3(HID / 256, Gg), 256, 0, s>>>(hg, cnt, HID);

    // ---- MLP head ----
    head_gemm<<<dim3((HID + 127) / 128, Gg), 128, HID * sizeof(float), s>>>(
        hg, fc1_w, fc1_b, t1, HID, HID, 1);
    head_gemm<<<dim3((MIDD + 127) / 128, Gg), 128, HID * sizeof(float), s>>>(
        t1, fc2_w, fc2_b, t2, HID, MIDD, 1);
    head_gemm<<<dim3(1, Gg), 128, MIDD * sizeof(float), s>>>(
        t2, fc3_w, fc3_b, out, MIDD, NCLS, 0);
}